// round 14
// baseline (speedup 1.0000x reference)
#include <cuda_runtime.h>
#include <cstdint>

typedef signed char s8;

#define HP0 516
#define HP1 260
#define HP2 132
#define HP3 68

// a0: [n][HP0][HP0][4] (u8-offset s8, pad=-128). a1..a3: chunk-major
// [n][c=IC/32][Hp][Wp][32] so 32B ic-chunks are contiguous across pixels.
__device__ __align__(16) s8 g_a0[4 * HP0 * HP0 * 4];
__device__ __align__(16) s8 g_a1[4 * HP1 * HP1 * 192];
__device__ __align__(16) s8 g_a2[4 * HP2 * HP2 * 192];
__device__ __align__(16) s8 g_a3[4 * HP3 * HP3 * 192];
__device__ __align__(16) s8 g_w0[192 * 25 * 4];
// mma fragment-packed weights: [octile64][chunk32][tap25][tp4][lane32][16B]
__device__ __align__(16) s8 g_w1[192 * 25 * 192];
__device__ __align__(16) s8 g_w2[192 * 25 * 192];
__device__ __align__(16) s8 g_w3[320 * 25 * 192];
__device__ int g_beff[4][320];
__device__ int g_muli[4][320];
__device__ int g_ctr[8];  // work-stealing counters, zeroed in k_prep1

__device__ __forceinline__ int ld_scalar(const int* p) {
    int v = *p;
    if ((unsigned)v >= 0x3f000000u) v = (int)rintf(__int_as_float(v));
    return v;
}

#define CP_ASYNC16(dst, src) \
    asm volatile("cp.async.cg.shared.global [%0], [%1], 16;" :: "r"(dst), "l"(src))
#define CP_ASYNC8(dst, src) \
    asm volatile("cp.async.ca.shared.global [%0], [%1], 8;" :: "r"(dst), "l"(src))
#define CP_COMMIT() asm volatile("cp.async.commit_group;" ::: "memory")
#define CP_WAIT1() asm volatile("cp.async.wait_group 1;" ::: "memory")

// ---------------- prep device helpers ----------------

__device__ __forceinline__ void d_quant(const float* __restrict__ x, int idx) {
    if (idx >= 4 * HP0 * HP0) return;
    int xp = idx % HP0;
    int t = idx / HP0;
    int yp = t % HP0;
    int n = t / HP0;
    unsigned v = 0x80808080u;
    if (yp >= 2 && yp < 514 && xp >= 2 && xp < 514) {
        int y = yp - 2, xx = xp - 2;
        unsigned b[3];
#pragma unroll
        for (int c = 0; c < 3; c++) {
            float f = x[((n * 3 + c) * 512 + y) * 512 + xx];
            float r = fminf(fmaxf(rintf(f * 256.f), 0.f), 255.f);
            b[c] = (unsigned)(((int)r - 128) & 0xff);
        }
        v = b[0] | (b[1] << 8) | (b[2] << 16) | 0x80000000u;
    }
    ((unsigned*)g_a0)[idx] = v;
}

// Fill only the 2-pixel pad border of a chunk-major buffer.
__device__ __forceinline__ void d_fillb(s8* buf, int Hp, int idx) {
    const int bw = Hp * Hp - (Hp - 4) * (Hp - 4);
    if (idx >= 24 * bw) return;
    int plane = idx / bw;
    int o = idx - plane * bw;
    const int top = 2 * Hp;
    int y, x;
    if (o < top) { y = o / Hp; x = o - (o / Hp) * Hp; }
    else if (o < 2 * top) { int t = o - top; y = Hp - 2 + t / Hp; x = t - (t / Hp) * Hp; }
    else { int t = o - 2 * top; int row = t >> 2; int c = t & 3;
           y = 2 + row; x = (c < 2) ? c : Hp - 4 + c; }
    uint4 v; v.x = v.y = v.z = v.w = 0x80808080u;
    uint4* p = (uint4*)(buf + (((size_t)plane * Hp + y) * Hp + x) * 32);
    p[0] = v; p[1] = v;
}

// paired-t fragment pack: byte idx -> [ot][ch][tap][tp][lane][half][word][j]
__device__ __forceinline__ void d_packb(const float* __restrict__ w,
                                        s8* __restrict__ wp, int idx, int total,
                                        int ICin) {
    if (idx >= total) return;
    int j = idx & 3;
    int word = (idx >> 2) & 1;
    int half = (idx >> 3) & 1;
    int l = (idx >> 4) & 31;
    int tp = (idx >> 9) & 3;
    int rest = idx >> 11;
    int tap = rest % 25; rest /= 25;
    int ch = rest % 6;
    int ot = rest / 6;
    int t = tp * 2 + half;
    int oc = ot * 64 + t * 8 + (l >> 2);
    int ic = ch * 32 + (l & 3) * 4 + word * 16 + j;
    wp[idx] = (s8)(int)rintf(w[(oc * ICin + ic) * 25 + tap]);
}

__device__ __forceinline__ void d_bias(const float* __restrict__ w,
                                       const float* __restrict__ bsrc,
                                       const float* __restrict__ mul, int layer,
                                       int ICin, int* red, int oc, int tid) {
    const float* wr = w + (size_t)oc * ICin * 25;
    int s = 0;
    for (int k = tid; k < ICin * 25; k += 256) s += (int)rintf(wr[k]);
    red[tid] = s;
    __syncthreads();
    for (int st = 128; st > 0; st >>= 1) {
        if (tid < st) red[tid] += red[tid + st];
        __syncthreads();
    }
    if (tid == 0) {
        g_beff[layer][oc] = (int)rintf(bsrc[oc]) + 128 * red[0];
        g_muli[layer][oc] = (int)rintf(mul[oc]);
    }
}

// prep1 (critical path): ctr reset + quant + border-fill a1 + layer0 pack/bias
__global__ void __launch_bounds__(256) k_prep1(
    const float* __restrict__ x, const float* __restrict__ w0,
    const float* __restrict__ b0, const float* __restrict__ mul0) {
    const int tid = threadIdx.x;
    int b = blockIdx.x;
    if (b < 4161) {
        if (b == 0 && tid < 8) g_ctr[tid] = 0;
        d_quant(x, b * 256 + tid);
        return;
    }
    b -= 4161;
    if (b < 194) { d_fillb(g_a1, HP1, b * 256 + tid); return; }
    b -= 194;
    {
        int pidx = b * 256 + tid;
        if (pidx < 192 * 25 * 4) {
            int byte = pidx & 3;
            int t = pidx >> 2;
            int oc_l = t & 63; t >>= 6;
            int tap = t % 25; t /= 25;
            int oc = t * 64 + oc_l;
            s8 val = 0;
            if (byte < 3) val = (s8)(int)rintf(w0[(oc * 3 + byte) * 25 + tap]);
            g_w0[pidx] = val;
        }
        if (pidx < 192) {
            const float* wr = w0 + (size_t)pidx * 75;
            int s = 0;
            for (int k = 0; k < 75; k++) s += (int)rintf(wr[k]);
            g_beff[0][pidx] = (int)rintf(b0[pidx] * 256.f) + 128 * s;
            g_muli[0][pidx] = (int)rintf(mul0[pidx]);
        }
    }
}

// prep2 (forked stream): w1 pack + fills a2/a3 + w2/w3 pack + bias1/2/3
// block budget: 3600 + 98 + 50 + 3600 + 6000 + 192 + 192 + 320 = 14052
__global__ void __launch_bounds__(256) k_prep2(
    const float* __restrict__ w1, const float* __restrict__ b1,
    const float* __restrict__ mul1,
    const float* __restrict__ w2, const float* __restrict__ b2,
    const float* __restrict__ mul2, const float* __restrict__ w3,
    const float* __restrict__ b3, const float* __restrict__ mul3) {
    const int tid = threadIdx.x;
    int b = blockIdx.x;
    __shared__ int red[256];
    if (b < 3600) { d_packb(w1, g_w1, b * 256 + tid, 921600, 192); return; }
    b -= 3600;
    if (b < 98) { d_fillb(g_a2, HP2, b * 256 + tid); return; }
    b -= 98;
    if (b < 50) { d_fillb(g_a3, HP3, b * 256 + tid); return; }
    b -= 50;
    if (b < 3600) { d_packb(w2, g_w2, b * 256 + tid, 921600, 192); return; }
    b -= 3600;
    if (b < 6000) { d_packb(w3, g_w3, b * 256 + tid, 1536000, 192); return; }
    b -= 6000;
    if (b < 192) { d_bias(w1, b1, mul1, 1, 192, red, b, tid); return; }
    b -= 192;
    if (b < 192) { d_bias(w2, b2, mul2, 2, 192, red, b, tid); return; }
    b -= 192;
    d_bias(w3, b3, mul3, 3, 192, red, b, tid);
}

// ---------------- layer 0: dp4a implicit conv (IC=4), int32 epilogue ------
__global__ void __launch_bounds__(256)
k_conv0(const s8* __restrict__ in, s8* __restrict__ out8,
        const s8* __restrict__ wgt,
        const int* __restrict__ mdp, const int* __restrict__ relup) {
    __shared__ __align__(16) int sW[25 * 64];
    __shared__ int sA[665];

    const int tid = threadIdx.x;
    const int r = tid >> 4;
    const int c = tid & 15;
    const int py = c & 7;
    const int x0 = (c >> 3) << 3;

    const int ocb = blockIdx.x << 6;
    const int by = blockIdx.y >> 4;
    const int bx = blockIdx.y & 15;
    const int oy0 = by << 3;
    const int ox0 = bx << 4;
    const int n = blockIdx.z;

    int acc[4][8];
#pragma unroll
    for (int i = 0; i < 4; i++)
#pragma unroll
        for (int j = 0; j < 8; j++) acc[i][j] = 0;

    const int aBase = (2 * py) * 35 + 2 * x0;
    const int iy0 = 2 * oy0, ix0 = 2 * ox0;

    {
        const int4* wsrc = (const int4*)(wgt + (size_t)blockIdx.x * (25 * 256));
        int4* wdst = (int4*)sW;
        for (int idx = tid; idx < 25 * 16; idx += 256) wdst[idx] = wsrc[idx];
        for (int idx = tid; idx < 665; idx += 256) {
            int iy = idx / 35, ix = idx - iy * 35;
            sA[idx] = *(const int*)(in + ((size_t)(n * HP0 + iy0 + iy) * HP0 + ix0 + ix) * 4);
        }
    }
    __syncthreads();

#pragma unroll
    for (int ky = 0; ky < 5; ky++)
#pragma unroll
        for (int kx = 0; kx < 5; kx++) {
            const int tap = ky * 5 + kx;
            const int4 w = ((const int4*)sW)[tap * 16 + r];
            const int* arow = &sA[ky * 35 + kx + aBase];
#pragma unroll
            for (int j = 0; j < 8; j++) {
                const int a = arow[2 * j];
                acc[0][j] = __dp4a(a, w.x, acc[0][j]);
                acc[1][j] = __dp4a(a, w.y, acc[1][j]);
                acc[2][j] = __dp4a(a, w.z, acc[2][j]);
                acc[3][j] = __dp4a(a, w.w, acc[3][j]);
            }
        }

    const int oy = oy0 + py;
    const int oxb = ox0 + x0;
    const int md = ld_scalar(mdp);
    const int relu = ld_scalar(relup);
    const int clp = (int)rint(255.0 * 16777216.0 / (double)relu);
    const int scl = (relu + 4) >> 3;
    const int sh1 = md;
    const int rnd1 = 1 << (sh1 - 1);

    int b[4], m[4];
#pragma unroll
    for (int i = 0; i < 4; i++) {
        int oc = ocb + r * 4 + i;
        b[i] = g_beff[0][oc];
        m[i] = g_muli[0][oc];
    }
    const int oc0 = ocb + r * 4;
    const int cch = oc0 >> 5;
    s8* obase = out8 + ((size_t)(n * 6 + cch) * HP1 + (oy + 2)) * (HP1 * 32) + (oc0 & 31);
#pragma unroll
    for (int j = 0; j < 8; j++) {
        unsigned pack = 0;
#pragma unroll
        for (int i = 0; i < 4; i++) {
            int v = (acc[i][j] + b[i]) * m[i];
            v = (v + rnd1) >> sh1;
            v = v < 0 ? 0 : (v > clp ? clp : v);
            v = (v * scl + (1 << 20)) >> 21;
            pack |= ((unsigned)((v - 128) & 0xff)) << (8 * i);
        }
        *(unsigned*)(obase + (size_t)(oxb + j + 2) * 32) = pack;
    }
}

// ---------------- layers 1-3: persistent pipelined int8 TC conv ----------
__device__ __forceinline__ void mma16832(int (&d)[4], const unsigned (&a)[4],
                                         unsigned bx, unsigned by) {
    asm volatile(
        "mma.sync.aligned.m16n8k32.row.col.s32.s8.s8.s32 "
        "{%0,%1,%2,%3}, {%4,%5,%6,%7}, {%8,%9}, {%0,%1,%2,%3};"
        : "+r"(d[0]), "+r"(d[1]), "+r"(d[2]), "+r"(d[3])
        : "r"(a[0]), "r"(a[1]), "r"(a[2]), "r"(a[3]), "r"(bx), "r"(by));
}

// TC=16: tile 8x16 px x 64 oc. TC=8: tile 8x8 px x 64 oc, warp pairs.
// Single-barrier 3-deep B ring (5-tap groups), A double-buffered.
// Work stealing: idx = base + atomicAdd(g_ctr[slot]); continue while idx < n_tiles.
#define BGRP 10240

template <int TC, bool FINAL>
__global__ void __launch_bounds__(256, 2)
k_mmap(const s8* __restrict__ in, int Hp,
       s8* __restrict__ out8, float* __restrict__ outf,
       int Hout, int Wout, int Hpo, int OC,
       const s8* __restrict__ wgt, int layer,
       const int* __restrict__ mdp, const int* __restrict__ relup,
       const int* __restrict__ gap, int n_tiles, int base, int slot) {
    constexpr bool PAIR = (TC == 8);
    constexpr int PCOLS = 2 * TC + 3;
    constexpr int NPIX = 19 * PCOLS;
    constexpr int ASZ = (NPIX * 40 + 127) & ~127;
    constexpr int BOFF = 2 * ASZ;
    constexpr int NT = PAIR ? 4 : 8;

    extern __shared__ __align__(16) unsigned char smem[];
    const uint32_t smem_sm = (uint32_t)__cvta_generic_to_shared(smem);
    __shared__ int s_tile;

    const int tid = threadIdx.x;
    const int w = tid >> 5;
    const int lane = tid & 31;
    const int gr = lane >> 2;
    const int qp = lane & 3;
    const int wp = PAIR ? (w & 3) : w;
    const int hi = PAIR ? (w >> 2) : 0;

    const int tiles_x = Wout / TC;
    const int tiles_y = Hout >> 3;
    const int per_oct = tiles_y * tiles_x * 4;

    const int md = ld_scalar(mdp);
    int ga = 0, relu = 0;
    if (FINAL) ga = ld_scalar(gap);
    else relu = ld_scalar(relup);

    const int abase = PAIR ? (((wp * 4) * PCOLS + (gr << 1)) * 10 + qp)
                           : (((w * 2) * PCOLS + (gr << 1)) * 10 + qp);
    constexpr int A1OFF = PAIR ? (2 * PCOLS * 10) : 160;
    int* ctr = &g_ctr[slot];

    while (true) {
        if (tid == 0) s_tile = base + atomicAdd(ctr, 1);
        __syncthreads();
        const int idx = s_tile;
        if (idx >= n_tiles) break;

        const int oct = idx / per_oct;
        int r1 = idx - oct * per_oct;
        const int by = r1 / (tiles_x * 4);
        int r2 = r1 - by * (tiles_x * 4);
        const int bx = r2 >> 2;
        const int n = r2 & 3;

        const int ocb = oct << 6;
        const int oy0 = by << 3;
        const int ox0 = bx * TC;
        const int iy0 = oy0 << 1, ix0 = ox0 << 1;

        int acc[NT][4];
#pragma unroll
        for (int t = 0; t < NT; t++)
#pragma unroll
            for (int k = 0; k < 4; k++) acc[t][k] = 0;

        const s8* wbase = wgt + (size_t)oct * 6 * 51200;
        {
            const int4* bs = (const int4*)wbase;
            for (int i = tid; i < 640; i += 256)
                CP_ASYNC16(smem_sm + BOFF + i * 16, bs + i);
            const s8* base_a =
                in + ((size_t)(n * 6 + 0) * Hp + iy0) * (size_t)(Hp * 32) +
                (size_t)ix0 * 32;
            for (int v = tid; v < NPIX * 4; v += 256) {
                int pix = v >> 2, part = v & 3;
                int iy = pix / PCOLS, ix = pix - iy * PCOLS;
                CP_ASYNC8(smem_sm + pix * 40 + part * 8,
                          base_a + ((size_t)iy * Hp + ix) * 32 + part * 8);
            }
            CP_COMMIT();
            const int4* bs1 = (const int4*)(wbase + BGRP);
            for (int i = tid; i < 640; i += 256)
                CP_ASYNC16(smem_sm + BOFF + BGRP + i * 16, bs1 + i);
            CP_COMMIT();
        }

        for (int u = 0; u < 30; u++) {
            CP_WAIT1();
            __syncthreads();
            if (u + 2 < 30) {
                const int un = u + 2;
                const int nch = un / 5, ng = un % 5;
                const int4* bs = (const int4*)(wbase + (size_t)nch * 51200 + ng * BGRP);
                const uint32_t bdst = smem_sm + BOFF + (un % 3) * BGRP;
                for (int i = tid; i < 640; i += 256)
                    CP_ASYNC16(bdst + i * 16, bs + i);
                if (ng == 0) {
                    const uint32_t adst = smem_sm + (nch & 1) * ASZ;
                    const s8* base_a =
                        in + ((size_t)(n * 6 + nch) * Hp + iy0) * (size_t)(Hp * 32) +
                        (size_t)ix0 * 32;
                    for (int v = tid; v < NPIX * 4; v += 256) {
                        int pix = v >> 2, part = v & 3;
                        int iy = pix / PCOLS, ix = pix - iy * PCOLS;
                        CP_ASYNC8(adst + pix * 40 + part * 8,
                                  base_a + ((size_t)iy * Hp + ix) * 32 + part * 8);
                    }
                }
            }
            CP_COMMIT();

            const int ch = u / 5, g = u % 5;
            const unsigned* aB = (const unsigned*)(smem + (ch & 1) * ASZ);
            const unsigned char* bB = smem + BOFF + (u % 3) * BGRP;
#pragma unroll
            for (int k = 0; k < 5; k++) {
                const unsigned* ap = aB + abase + (g * PCOLS + k) * 10;
                unsigned a[4];
                a[0] = ap[0];
                a[2] = ap[4];
                a[1] = ap[A1OFF];
                a[3] = ap[A1OFF + 4];
                const uint4* bq = (const uint4*)(bB + k * 2048) + lane;
                if (PAIR) {
#pragma unroll
                    for (int tp2 = 0; tp2 < 2; tp2++) {
                        uint4 bb = bq[(hi * 2 + tp2) * 32];
                        mma16832(acc[2 * tp2], a, bb.x, bb.y);
                        mma16832(acc[2 * tp2 + 1], a, bb.z, bb.w);
                    }
                } else {
#pragma unroll
                    for (int tp = 0; tp < 4; tp++) {
                        uint4 bb = bq[tp * 32];
                        mma16832(acc[2 * tp], a, bb.x, bb.y);
                        mma16832(acc[2 * tp + 1], a, bb.z, bb.w);
                    }
                }
            }
        }

        if (FINAL) {
            const int sh = md - ga;
            const long long rnd = 1LL << (sh - 1);
#pragma unroll
            for (int t = 0; t < NT; t++) {
                int tg = PAIR ? (4 * hi + t) : t;
                int oc = ocb + tg * 8 + 2 * qp;
                int2 bb = *(const int2*)&g_beff[layer][oc];
                int2 mm = *(const int2*)&g_muli[layer][oc];
#pragma unroll
                for (int half = 0; half < 2; half++) {
                    int oy = PAIR ? (oy0 + 2 * wp + half) : (oy0 + w);
                    int ox = PAIR ? (ox0 + gr) : (ox0 + gr + half * 8);
                    long long v0 = ((long long)acc[t][half * 2] + bb.x) * mm.x;
                    long long v1 = ((long long)acc[t][half * 2 + 1] + bb.y) * mm.y;
                    v0 = (v0 + rnd) >> sh;
                    v1 = (v1 + rnd) >> sh;
                    outf[(((size_t)n * OC + oc) * Hout + oy) * Wout + ox] = (float)v0;
                    outf[(((size_t)n * OC + oc + 1) * Hout + oy) * Wout + ox] = (float)v1;
                }
            }
        } else {
            const long long clp = (long long)rint(255.0 * 16777216.0 / (double)relu);
            const long long scl = (long long)((relu + 4) >> 3);
            const int sh1 = md - 8;
            const long long rnd1 = 1LL << (sh1 - 1);
#pragma unroll
            for (int t = 0; t < NT; t++) {
                int tg = PAIR ? (4 * hi + t) : t;
                int oc = ocb + tg * 8 + 2 * qp;
                int2 bb = *(const int2*)&g_beff[layer][oc];
                int2 mm = *(const int2*)&g_muli[layer][oc];
                s8* ob = out8 + ((size_t)(n * 6 + (oc >> 5)) * Hpo) * (size_t)(Hpo * 32) +
                         (oc & 31);
#pragma unroll
                for (int half = 0; half < 2; half++) {
                    int oy = PAIR ? (oy0 + 2 * wp + half) : (oy0 + w);
                    int ox = PAIR ? (ox0 + gr) : (ox0 + gr + half * 8);
                    long long v0 = ((long long)acc[t][half * 2] + bb.x) * mm.x;
                    long long v1 = ((long long)acc[t][half * 2 + 1] + bb.y) * mm.y;
                    v0 = (v0 + rnd1) >> sh1;
                    v1 = (v1 + rnd1) >> sh1;
                    v0 = v0 < 0 ? 0 : (v0 > clp ? clp : v0);
                    v1 = v1 < 0 ? 0 : (v1 > clp ? clp : v1);
                    v0 = (v0 * scl + (1LL << 20)) >> 21;
                    v1 = (v1 * scl + (1LL << 20)) >> 21;
                    unsigned short pk =
                        (unsigned short)(((unsigned)((v0 - 128) & 0xff)) |
                                         (((unsigned)((v1 - 128) & 0xff)) << 8));
                    *(unsigned short*)(ob + ((size_t)(oy + 2) * Hpo + (ox + 2)) * 32) = pk;
                }
            }
        }
    }
}

extern "C" void kernel_launch(void* const* d_in, const int* in_sizes, int n_in,
                              void* d_out, int out_size) {
    const float* x = (const float*)d_in[0];
    const float* w0 = (const float*)d_in[1];
    const float* b0 = (const float*)d_in[2];
    const float* w1 = (const float*)d_in[3];
    const float* b1 = (const float*)d_in[4];
    const float* w2 = (const float*)d_in[5];
    const float* b2 = (const float*)d_in[6];
    const float* w3 = (const float*)d_in[7];
    const float* b3 = (const float*)d_in[8];
    const float* mul0 = (const float*)d_in[9];
    const float* mul1 = (const float*)d_in[10];
    const float* mul2 = (const float*)d_in[11];
    const float* mul3 = (const float*)d_in[12];
    const int* relu0 = (const int*)d_in[13];
    const int* relu1 = (const int*)d_in[14];
    const int* relu2 = (const int*)d_in[15];
    const int* md0 = (const int*)d_in[16];
    const int* md1 = (const int*)d_in[17];
    const int* md2 = (const int*)d_in[18];
    const int* md3 = (const int*)d_in[19];
    const int* ga = (const int*)d_in[20];
    (void)in_sizes; (void)n_in; (void)out_size;

    static s8 *a0 = nullptr, *a1, *a2, *a3, *w0p, *w1p, *w2p, *w3p;
    static cudaStream_t s2 = nullptr;
    static cudaEvent_t ev0 = nullptr, ev2 = nullptr;
    const int SM16 = 2 * 26624 + 3 * BGRP;   // 83968
    const int SM8 = 2 * 14464 + 3 * BGRP;    // 59648
    if (!a0) {
        cudaGetSymbolAddress((void**)&a0, g_a0);
        cudaGetSymbolAddress((void**)&a1, g_a1);
        cudaGetSymbolAddress((void**)&a2, g_a2);
        cudaGetSymbolAddress((void**)&a3, g_a3);
        cudaGetSymbolAddress((void**)&w0p, g_w0);
        cudaGetSymbolAddress((void**)&w1p, g_w1);
        cudaGetSymbolAddress((void**)&w2p, g_w2);
        cudaGetSymbolAddress((void**)&w3p, g_w3);
        cudaStreamCreateWithFlags(&s2, cudaStreamNonBlocking);
        cudaEventCreateWithFlags(&ev0, cudaEventDisableTiming);
        cudaEventCreateWithFlags(&ev2, cudaEventDisableTiming);
        cudaFuncSetAttribute(k_mmap<16, false>,
                             cudaFuncAttributeMaxDynamicSharedMemorySize, SM16);
        cudaFuncSetAttribute(k_mmap<8, false>,
                             cudaFuncAttributeMaxDynamicSharedMemorySize, SM8);
        cudaFuncSetAttribute(k_mmap<8, true>,
                             cudaFuncAttributeMaxDynamicSharedMemorySize, SM8);
    }

    // capture-legal fork: event originates on the capture (default) stream
    cudaEventRecord(ev0, 0);
    cudaStreamWaitEvent(s2, ev0, 0);
    k_prep2<<<14052, 256, 0, s2>>>(w1, b1, mul1, w2, b2, mul2, w3, b3, mul3);
    cudaEventRecord(ev2, s2);

    k_prep1<<<4430, 256>>>(x, w0, b0, mul0);
    k_conv0<<<dim3(3, 512, 4), 256>>>(a0, a1, w0p, md0, relu0);
    cudaStreamWaitEvent(0, ev2, 0);  // join: w1/w2/w3 packs + fills + biases ready
    // L1 main: exactly 5 tiles per CTA-slot (304*5 = 1520), zero tail
    k_mmap<16, false><<<304, 256, SM16>>>(a1, HP1, a2, nullptr,
        128, 128, HP2, 192, w1p, 1, md1, relu1, nullptr, 1520, 0, 1);  // profiled
    // L1 tail: TC16 idx 1520..1535 == TC8 idx 3040..3071 (verified decode)
    k_mmap<8, false><<<304, 256, SM8>>>(a1, HP1, a2, nullptr,
        128, 128, HP2, 192, w1p, 1, md1, relu1, nullptr, 3072, 3040, 5);
    k_mmap<8, false><<<304, 256, SM8>>>(a2, HP2, a3, nullptr,
        64, 64, HP3, 192, w2p, 2, md2, relu2, nullptr, 768, 0, 2);
    k_mmap<8, true><<<304, 256, SM8>>>(a3, HP3, nullptr, (float*)d_out,
        32, 32, 0, 320, w3p, 3, md3, nullptr, ga, 320, 0, 3);
}

// round 15
// speedup vs baseline: 1.0309x; 1.0309x over previous
#include <cuda_runtime.h>
#include <cstdint>

typedef signed char s8;

#define HP0 516
#define HP1 260
#define HP2 132
#define HP3 68

// a0: [n][HP0][HP0][4] (u8-offset s8, pad=-128). a1..a3: chunk-major
// [n][c=IC/32][Hp][Wp][32] so 32B ic-chunks are contiguous across pixels.
__device__ __align__(16) s8 g_a0[4 * HP0 * HP0 * 4];
__device__ __align__(16) s8 g_a1[4 * HP1 * HP1 * 192];
__device__ __align__(16) s8 g_a2[4 * HP2 * HP2 * 192];
__device__ __align__(16) s8 g_a3[4 * HP3 * HP3 * 192];
__device__ __align__(16) s8 g_w0[192 * 25 * 4];
// mma fragment-packed weights: [octile64][chunk32][tap25][tp4][lane32][16B]
__device__ __align__(16) s8 g_w1[192 * 25 * 192];
__device__ __align__(16) s8 g_w2[192 * 25 * 192];
__device__ __align__(16) s8 g_w3[320 * 25 * 192];
__device__ int g_beff[4][320];
__device__ int g_muli[4][320];
__device__ int g_ctr[8];  // work-stealing counters, zeroed in k_prep1

__device__ __forceinline__ int ld_scalar(const int* p) {
    int v = *p;
    if ((unsigned)v >= 0x3f000000u) v = (int)rintf(__int_as_float(v));
    return v;
}

#define CP_ASYNC16(dst, src) \
    asm volatile("cp.async.cg.shared.global [%0], [%1], 16;" :: "r"(dst), "l"(src))
#define CP_ASYNC8(dst, src) \
    asm volatile("cp.async.ca.shared.global [%0], [%1], 8;" :: "r"(dst), "l"(src))
#define CP_COMMIT() asm volatile("cp.async.commit_group;" ::: "memory")
#define CP_WAIT1() asm volatile("cp.async.wait_group 1;" ::: "memory")

// ---------------- prep device helpers ----------------

__device__ __forceinline__ void d_quant(const float* __restrict__ x, int idx) {
    if (idx >= 4 * HP0 * HP0) return;
    int xp = idx % HP0;
    int t = idx / HP0;
    int yp = t % HP0;
    int n = t / HP0;
    unsigned v = 0x80808080u;
    if (yp >= 2 && yp < 514 && xp >= 2 && xp < 514) {
        int y = yp - 2, xx = xp - 2;
        unsigned b[3];
#pragma unroll
        for (int c = 0; c < 3; c++) {
            float f = x[((n * 3 + c) * 512 + y) * 512 + xx];
            float r = fminf(fmaxf(rintf(f * 256.f), 0.f), 255.f);
            b[c] = (unsigned)(((int)r - 128) & 0xff);
        }
        v = b[0] | (b[1] << 8) | (b[2] << 16) | 0x80000000u;
    }
    ((unsigned*)g_a0)[idx] = v;
}

// Fill only the 2-pixel pad border of a chunk-major buffer.
__device__ __forceinline__ void d_fillb(s8* buf, int Hp, int idx) {
    const int bw = Hp * Hp - (Hp - 4) * (Hp - 4);
    if (idx >= 24 * bw) return;
    int plane = idx / bw;
    int o = idx - plane * bw;
    const int top = 2 * Hp;
    int y, x;
    if (o < top) { y = o / Hp; x = o - (o / Hp) * Hp; }
    else if (o < 2 * top) { int t = o - top; y = Hp - 2 + t / Hp; x = t - (t / Hp) * Hp; }
    else { int t = o - 2 * top; int row = t >> 2; int c = t & 3;
           y = 2 + row; x = (c < 2) ? c : Hp - 4 + c; }
    uint4 v; v.x = v.y = v.z = v.w = 0x80808080u;
    uint4* p = (uint4*)(buf + (((size_t)plane * Hp + y) * Hp + x) * 32);
    p[0] = v; p[1] = v;
}

// paired-t fragment pack: byte idx -> [ot][ch][tap][tp][lane][half][word][j]
__device__ __forceinline__ void d_packb(const float* __restrict__ w,
                                        s8* __restrict__ wp, int idx, int total,
                                        int ICin) {
    if (idx >= total) return;
    int j = idx & 3;
    int word = (idx >> 2) & 1;
    int half = (idx >> 3) & 1;
    int l = (idx >> 4) & 31;
    int tp = (idx >> 9) & 3;
    int rest = idx >> 11;
    int tap = rest % 25; rest /= 25;
    int ch = rest % 6;
    int ot = rest / 6;
    int t = tp * 2 + half;
    int oc = ot * 64 + t * 8 + (l >> 2);
    int ic = ch * 32 + (l & 3) * 4 + word * 16 + j;
    wp[idx] = (s8)(int)rintf(w[(oc * ICin + ic) * 25 + tap]);
}

__device__ __forceinline__ void d_bias(const float* __restrict__ w,
                                       const float* __restrict__ bsrc,
                                       const float* __restrict__ mul, int layer,
                                       int ICin, int* red, int oc, int tid) {
    const float* wr = w + (size_t)oc * ICin * 25;
    int s = 0;
    for (int k = tid; k < ICin * 25; k += 256) s += (int)rintf(wr[k]);
    red[tid] = s;
    __syncthreads();
    for (int st = 128; st > 0; st >>= 1) {
        if (tid < st) red[tid] += red[tid + st];
        __syncthreads();
    }
    if (tid == 0) {
        g_beff[layer][oc] = (int)rintf(bsrc[oc]) + 128 * red[0];
        g_muli[layer][oc] = (int)rintf(mul[oc]);
    }
}

// prep1 (critical path): ctr reset + quant + border-fill a1 + layer0 pack/bias
__global__ void __launch_bounds__(256) k_prep1(
    const float* __restrict__ x, const float* __restrict__ w0,
    const float* __restrict__ b0, const float* __restrict__ mul0) {
    const int tid = threadIdx.x;
    int b = blockIdx.x;
    if (b < 4161) {
        if (b == 0 && tid < 8) g_ctr[tid] = 0;
        d_quant(x, b * 256 + tid);
        return;
    }
    b -= 4161;
    if (b < 194) { d_fillb(g_a1, HP1, b * 256 + tid); return; }
    b -= 194;
    {
        int pidx = b * 256 + tid;
        if (pidx < 192 * 25 * 4) {
            int byte = pidx & 3;
            int t = pidx >> 2;
            int oc_l = t & 63; t >>= 6;
            int tap = t % 25; t /= 25;
            int oc = t * 64 + oc_l;
            s8 val = 0;
            if (byte < 3) val = (s8)(int)rintf(w0[(oc * 3 + byte) * 25 + tap]);
            g_w0[pidx] = val;
        }
        if (pidx < 192) {
            const float* wr = w0 + (size_t)pidx * 75;
            int s = 0;
            for (int k = 0; k < 75; k++) s += (int)rintf(wr[k]);
            g_beff[0][pidx] = (int)rintf(b0[pidx] * 256.f) + 128 * s;
            g_muli[0][pidx] = (int)rintf(mul0[pidx]);
        }
    }
}

// prep2a (forked stream, joined before L1): w1 pack + bias1. 3600+192 = 3792 blocks
__global__ void __launch_bounds__(256) k_prep2a(
    const float* __restrict__ w1, const float* __restrict__ b1,
    const float* __restrict__ mul1) {
    const int tid = threadIdx.x;
    int b = blockIdx.x;
    __shared__ int red[256];
    if (b < 3600) { d_packb(w1, g_w1, b * 256 + tid, 921600, 192); return; }
    b -= 3600;
    d_bias(w1, b1, mul1, 1, 192, red, b, tid);
}

// prep2b (forked stream, joined before L2): fills a2/a3 + w2/w3 pack + bias2/3
// 98 + 50 + 3600 + 6000 + 192 + 320 = 10260 blocks
__global__ void __launch_bounds__(256) k_prep2b(
    const float* __restrict__ w2, const float* __restrict__ b2,
    const float* __restrict__ mul2, const float* __restrict__ w3,
    const float* __restrict__ b3, const float* __restrict__ mul3) {
    const int tid = threadIdx.x;
    int b = blockIdx.x;
    __shared__ int red[256];
    if (b < 98) { d_fillb(g_a2, HP2, b * 256 + tid); return; }
    b -= 98;
    if (b < 50) { d_fillb(g_a3, HP3, b * 256 + tid); return; }
    b -= 50;
    if (b < 3600) { d_packb(w2, g_w2, b * 256 + tid, 921600, 192); return; }
    b -= 3600;
    if (b < 6000) { d_packb(w3, g_w3, b * 256 + tid, 1536000, 192); return; }
    b -= 6000;
    if (b < 192) { d_bias(w2, b2, mul2, 2, 192, red, b, tid); return; }
    b -= 192;
    d_bias(w3, b3, mul3, 3, 192, red, b, tid);
}

// ---------------- layer 0: dp4a implicit conv (IC=4), int32 epilogue ------
__global__ void __launch_bounds__(256)
k_conv0(const s8* __restrict__ in, s8* __restrict__ out8,
        const s8* __restrict__ wgt,
        const int* __restrict__ mdp, const int* __restrict__ relup) {
    __shared__ __align__(16) int sW[25 * 64];
    __shared__ int sA[665];

    const int tid = threadIdx.x;
    const int r = tid >> 4;
    const int c = tid & 15;
    const int py = c & 7;
    const int x0 = (c >> 3) << 3;

    const int ocb = blockIdx.x << 6;
    const int by = blockIdx.y >> 4;
    const int bx = blockIdx.y & 15;
    const int oy0 = by << 3;
    const int ox0 = bx << 4;
    const int n = blockIdx.z;

    int acc[4][8];
#pragma unroll
    for (int i = 0; i < 4; i++)
#pragma unroll
        for (int j = 0; j < 8; j++) acc[i][j] = 0;

    const int aBase = (2 * py) * 35 + 2 * x0;
    const int iy0 = 2 * oy0, ix0 = 2 * ox0;

    {
        const int4* wsrc = (const int4*)(wgt + (size_t)blockIdx.x * (25 * 256));
        int4* wdst = (int4*)sW;
        for (int idx = tid; idx < 25 * 16; idx += 256) wdst[idx] = wsrc[idx];
        for (int idx = tid; idx < 665; idx += 256) {
            int iy = idx / 35, ix = idx - iy * 35;
            sA[idx] = *(const int*)(in + ((size_t)(n * HP0 + iy0 + iy) * HP0 + ix0 + ix) * 4);
        }
    }
    __syncthreads();

#pragma unroll
    for (int ky = 0; ky < 5; ky++)
#pragma unroll
        for (int kx = 0; kx < 5; kx++) {
            const int tap = ky * 5 + kx;
            const int4 w = ((const int4*)sW)[tap * 16 + r];
            const int* arow = &sA[ky * 35 + kx + aBase];
#pragma unroll
            for (int j = 0; j < 8; j++) {
                const int a = arow[2 * j];
                acc[0][j] = __dp4a(a, w.x, acc[0][j]);
                acc[1][j] = __dp4a(a, w.y, acc[1][j]);
                acc[2][j] = __dp4a(a, w.z, acc[2][j]);
                acc[3][j] = __dp4a(a, w.w, acc[3][j]);
            }
        }

    const int oy = oy0 + py;
    const int oxb = ox0 + x0;
    const int md = ld_scalar(mdp);
    const int relu = ld_scalar(relup);
    const int clp = (int)rint(255.0 * 16777216.0 / (double)relu);
    const int scl = (relu + 4) >> 3;
    const int sh1 = md;
    const int rnd1 = 1 << (sh1 - 1);

    int b[4], m[4];
#pragma unroll
    for (int i = 0; i < 4; i++) {
        int oc = ocb + r * 4 + i;
        b[i] = g_beff[0][oc];
        m[i] = g_muli[0][oc];
    }
    const int oc0 = ocb + r * 4;
    const int cch = oc0 >> 5;
    s8* obase = out8 + ((size_t)(n * 6 + cch) * HP1 + (oy + 2)) * (HP1 * 32) + (oc0 & 31);
#pragma unroll
    for (int j = 0; j < 8; j++) {
        unsigned pack = 0;
#pragma unroll
        for (int i = 0; i < 4; i++) {
            int v = (acc[i][j] + b[i]) * m[i];
            v = (v + rnd1) >> sh1;
            v = v < 0 ? 0 : (v > clp ? clp : v);
            v = (v * scl + (1 << 20)) >> 21;
            pack |= ((unsigned)((v - 128) & 0xff)) << (8 * i);
        }
        *(unsigned*)(obase + (size_t)(oxb + j + 2) * 32) = pack;
    }
}

// ---------------- layers 1-3: persistent pipelined int8 TC conv ----------
__device__ __forceinline__ void mma16832(int (&d)[4], const unsigned (&a)[4],
                                         unsigned bx, unsigned by) {
    asm volatile(
        "mma.sync.aligned.m16n8k32.row.col.s32.s8.s8.s32 "
        "{%0,%1,%2,%3}, {%4,%5,%6,%7}, {%8,%9}, {%0,%1,%2,%3};"
        : "+r"(d[0]), "+r"(d[1]), "+r"(d[2]), "+r"(d[3])
        : "r"(a[0]), "r"(a[1]), "r"(a[2]), "r"(a[3]), "r"(bx), "r"(by));
}

// TC=16: tile 8x16 px x 64 oc. TC=8: tile 8x8 px x 64 oc, warp pairs.
// Single-barrier 3-deep B ring (5-tap groups), A double-buffered.
// Work stealing: idx = base + atomicAdd(g_ctr[slot]); continue while idx < n_tiles.
#define BGRP 10240

template <int TC, bool FINAL>
__global__ void __launch_bounds__(256, 2)
k_mmap(const s8* __restrict__ in, int Hp,
       s8* __restrict__ out8, float* __restrict__ outf,
       int Hout, int Wout, int Hpo, int OC,
       const s8* __restrict__ wgt, int layer,
       const int* __restrict__ mdp, const int* __restrict__ relup,
       const int* __restrict__ gap, int n_tiles, int base, int slot) {
    constexpr bool PAIR = (TC == 8);
    constexpr int PCOLS = 2 * TC + 3;
    constexpr int NPIX = 19 * PCOLS;
    constexpr int ASZ = (NPIX * 40 + 127) & ~127;
    constexpr int BOFF = 2 * ASZ;
    constexpr int NT = PAIR ? 4 : 8;

    extern __shared__ __align__(16) unsigned char smem[];
    const uint32_t smem_sm = (uint32_t)__cvta_generic_to_shared(smem);
    __shared__ int s_tile;

    const int tid = threadIdx.x;
    const int w = tid >> 5;
    const int lane = tid & 31;
    const int gr = lane >> 2;
    const int qp = lane & 3;
    const int wp = PAIR ? (w & 3) : w;
    const int hi = PAIR ? (w >> 2) : 0;

    const int tiles_x = Wout / TC;
    const int tiles_y = Hout >> 3;
    const int per_oct = tiles_y * tiles_x * 4;

    const int md = ld_scalar(mdp);
    int ga = 0, relu = 0;
    if (FINAL) ga = ld_scalar(gap);
    else relu = ld_scalar(relup);

    const int abase = PAIR ? (((wp * 4) * PCOLS + (gr << 1)) * 10 + qp)
                           : (((w * 2) * PCOLS + (gr << 1)) * 10 + qp);
    constexpr int A1OFF = PAIR ? (2 * PCOLS * 10) : 160;
    int* ctr = &g_ctr[slot];

    while (true) {
        if (tid == 0) s_tile = base + atomicAdd(ctr, 1);
        __syncthreads();
        const int idx = s_tile;
        if (idx >= n_tiles) break;

        const int oct = idx / per_oct;
        int r1 = idx - oct * per_oct;
        const int by = r1 / (tiles_x * 4);
        int r2 = r1 - by * (tiles_x * 4);
        const int bx = r2 >> 2;
        const int n = r2 & 3;

        const int ocb = oct << 6;
        const int oy0 = by << 3;
        const int ox0 = bx * TC;
        const int iy0 = oy0 << 1, ix0 = ox0 << 1;

        int acc[NT][4];
#pragma unroll
        for (int t = 0; t < NT; t++)
#pragma unroll
            for (int k = 0; k < 4; k++) acc[t][k] = 0;

        const s8* wbase = wgt + (size_t)oct * 6 * 51200;
        {
            const int4* bs = (const int4*)wbase;
            for (int i = tid; i < 640; i += 256)
                CP_ASYNC16(smem_sm + BOFF + i * 16, bs + i);
            const s8* base_a =
                in + ((size_t)(n * 6 + 0) * Hp + iy0) * (size_t)(Hp * 32) +
                (size_t)ix0 * 32;
            for (int v = tid; v < NPIX * 4; v += 256) {
                int pix = v >> 2, part = v & 3;
                int iy = pix / PCOLS, ix = pix - iy * PCOLS;
                CP_ASYNC8(smem_sm + pix * 40 + part * 8,
                          base_a + ((size_t)iy * Hp + ix) * 32 + part * 8);
            }
            CP_COMMIT();
            const int4* bs1 = (const int4*)(wbase + BGRP);
            for (int i = tid; i < 640; i += 256)
                CP_ASYNC16(smem_sm + BOFF + BGRP + i * 16, bs1 + i);
            CP_COMMIT();
        }

        for (int u = 0; u < 30; u++) {
            CP_WAIT1();
            __syncthreads();
            if (u + 2 < 30) {
                const int un = u + 2;
                const int nch = un / 5, ng = un % 5;
                const int4* bs = (const int4*)(wbase + (size_t)nch * 51200 + ng * BGRP);
                const uint32_t bdst = smem_sm + BOFF + (un % 3) * BGRP;
                for (int i = tid; i < 640; i += 256)
                    CP_ASYNC16(bdst + i * 16, bs + i);
                if (ng == 0) {
                    const uint32_t adst = smem_sm + (nch & 1) * ASZ;
                    const s8* base_a =
                        in + ((size_t)(n * 6 + nch) * Hp + iy0) * (size_t)(Hp * 32) +
                        (size_t)ix0 * 32;
                    for (int v = tid; v < NPIX * 4; v += 256) {
                        int pix = v >> 2, part = v & 3;
                        int iy = pix / PCOLS, ix = pix - iy * PCOLS;
                        CP_ASYNC8(adst + pix * 40 + part * 8,
                                  base_a + ((size_t)iy * Hp + ix) * 32 + part * 8);
                    }
                }
            }
            CP_COMMIT();

            const int ch = u / 5, g = u % 5;
            const unsigned* aB = (const unsigned*)(smem + (ch & 1) * ASZ);
            const unsigned char* bB = smem + BOFF + (u % 3) * BGRP;
#pragma unroll
            for (int k = 0; k < 5; k++) {
                const unsigned* ap = aB + abase + (g * PCOLS + k) * 10;
                unsigned a[4];
                a[0] = ap[0];
                a[2] = ap[4];
                a[1] = ap[A1OFF];
                a[3] = ap[A1OFF + 4];
                const uint4* bq = (const uint4*)(bB + k * 2048) + lane;
                if (PAIR) {
#pragma unroll
                    for (int tp2 = 0; tp2 < 2; tp2++) {
                        uint4 bb = bq[(hi * 2 + tp2) * 32];
                        mma16832(acc[2 * tp2], a, bb.x, bb.y);
                        mma16832(acc[2 * tp2 + 1], a, bb.z, bb.w);
                    }
                } else {
#pragma unroll
                    for (int tp = 0; tp < 4; tp++) {
                        uint4 bb = bq[tp * 32];
                        mma16832(acc[2 * tp], a, bb.x, bb.y);
                        mma16832(acc[2 * tp + 1], a, bb.z, bb.w);
                    }
                }
            }
        }

        if (FINAL) {
            const int sh = md - ga;
            const long long rnd = 1LL << (sh - 1);
#pragma unroll
            for (int t = 0; t < NT; t++) {
                int tg = PAIR ? (4 * hi + t) : t;
                int oc = ocb + tg * 8 + 2 * qp;
                int2 bb = *(const int2*)&g_beff[layer][oc];
                int2 mm = *(const int2*)&g_muli[layer][oc];
#pragma unroll
                for (int half = 0; half < 2; half++) {
                    int oy = PAIR ? (oy0 + 2 * wp + half) : (oy0 + w);
                    int ox = PAIR ? (ox0 + gr) : (ox0 + gr + half * 8);
                    long long v0 = ((long long)acc[t][half * 2] + bb.x) * mm.x;
                    long long v1 = ((long long)acc[t][half * 2 + 1] + bb.y) * mm.y;
                    v0 = (v0 + rnd) >> sh;
                    v1 = (v1 + rnd) >> sh;
                    outf[(((size_t)n * OC + oc) * Hout + oy) * Wout + ox] = (float)v0;
                    outf[(((size_t)n * OC + oc + 1) * Hout + oy) * Wout + ox] = (float)v1;
                }
            }
        } else {
            const long long clp = (long long)rint(255.0 * 16777216.0 / (double)relu);
            const long long scl = (long long)((relu + 4) >> 3);
            const int sh1 = md - 8;
            const long long rnd1 = 1LL << (sh1 - 1);
#pragma unroll
            for (int t = 0; t < NT; t++) {
                int tg = PAIR ? (4 * hi + t) : t;
                int oc = ocb + tg * 8 + 2 * qp;
                int2 bb = *(const int2*)&g_beff[layer][oc];
                int2 mm = *(const int2*)&g_muli[layer][oc];
                s8* ob = out8 + ((size_t)(n * 6 + (oc >> 5)) * Hpo) * (size_t)(Hpo * 32) +
                         (oc & 31);
#pragma unroll
                for (int half = 0; half < 2; half++) {
                    int oy = PAIR ? (oy0 + 2 * wp + half) : (oy0 + w);
                    int ox = PAIR ? (ox0 + gr) : (ox0 + gr + half * 8);
                    long long v0 = ((long long)acc[t][half * 2] + bb.x) * mm.x;
                    long long v1 = ((long long)acc[t][half * 2 + 1] + bb.y) * mm.y;
                    v0 = (v0 + rnd1) >> sh1;
                    v1 = (v1 + rnd1) >> sh1;
                    v0 = v0 < 0 ? 0 : (v0 > clp ? clp : v0);
                    v1 = v1 < 0 ? 0 : (v1 > clp ? clp : v1);
                    v0 = (v0 * scl + (1LL << 20)) >> 21;
                    v1 = (v1 * scl + (1LL << 20)) >> 21;
                    unsigned short pk =
                        (unsigned short)(((unsigned)((v0 - 128) & 0xff)) |
                                         (((unsigned)((v1 - 128) & 0xff)) << 8));
                    *(unsigned short*)(ob + ((size_t)(oy + 2) * Hpo + (ox + 2)) * 32) = pk;
                }
            }
        }
    }
}

extern "C" void kernel_launch(void* const* d_in, const int* in_sizes, int n_in,
                              void* d_out, int out_size) {
    const float* x = (const float*)d_in[0];
    const float* w0 = (const float*)d_in[1];
    const float* b0 = (const float*)d_in[2];
    const float* w1 = (const float*)d_in[3];
    const float* b1 = (const float*)d_in[4];
    const float* w2 = (const float*)d_in[5];
    const float* b2 = (const float*)d_in[6];
    const float* w3 = (const float*)d_in[7];
    const float* b3 = (const float*)d_in[8];
    const float* mul0 = (const float*)d_in[9];
    const float* mul1 = (const float*)d_in[10];
    const float* mul2 = (const float*)d_in[11];
    const float* mul3 = (const float*)d_in[12];
    const int* relu0 = (const int*)d_in[13];
    const int* relu1 = (const int*)d_in[14];
    const int* relu2 = (const int*)d_in[15];
    const int* md0 = (const int*)d_in[16];
    const int* md1 = (const int*)d_in[17];
    const int* md2 = (const int*)d_in[18];
    const int* md3 = (const int*)d_in[19];
    const int* ga = (const int*)d_in[20];
    (void)in_sizes; (void)n_in; (void)out_size;

    static s8 *a0 = nullptr, *a1, *a2, *a3, *w0p, *w1p, *w2p, *w3p;
    static cudaStream_t s2 = nullptr;
    static cudaEvent_t ev0 = nullptr, ev2a = nullptr, ev2b = nullptr;
    const int SM16 = 2 * 26624 + 3 * BGRP;   // 83968
    const int SM8 = 2 * 14464 + 3 * BGRP;    // 59648
    if (!a0) {
        cudaGetSymbolAddress((void**)&a0, g_a0);
        cudaGetSymbolAddress((void**)&a1, g_a1);
        cudaGetSymbolAddress((void**)&a2, g_a2);
        cudaGetSymbolAddress((void**)&a3, g_a3);
        cudaGetSymbolAddress((void**)&w0p, g_w0);
        cudaGetSymbolAddress((void**)&w1p, g_w1);
        cudaGetSymbolAddress((void**)&w2p, g_w2);
        cudaGetSymbolAddress((void**)&w3p, g_w3);
        cudaStreamCreateWithFlags(&s2, cudaStreamNonBlocking);
        cudaEventCreateWithFlags(&ev0, cudaEventDisableTiming);
        cudaEventCreateWithFlags(&ev2a, cudaEventDisableTiming);
        cudaEventCreateWithFlags(&ev2b, cudaEventDisableTiming);
        cudaFuncSetAttribute(k_mmap<16, false>,
                             cudaFuncAttributeMaxDynamicSharedMemorySize, SM16);
        cudaFuncSetAttribute(k_mmap<8, false>,
                             cudaFuncAttributeMaxDynamicSharedMemorySize, SM8);
        cudaFuncSetAttribute(k_mmap<8, true>,
                             cudaFuncAttributeMaxDynamicSharedMemorySize, SM8);
    }

    // capture-legal fork: prep2a (needed by L1) then prep2b (needed by L2/L3)
    cudaEventRecord(ev0, 0);
    cudaStreamWaitEvent(s2, ev0, 0);
    k_prep2a<<<3792, 256, 0, s2>>>(w1, b1, mul1);
    cudaEventRecord(ev2a, s2);
    k_prep2b<<<10260, 256, 0, s2>>>(w2, b2, mul2, w3, b3, mul3);
    cudaEventRecord(ev2b, s2);

    k_prep1<<<4430, 256>>>(x, w0, b0, mul0);
    k_conv0<<<dim3(3, 512, 4), 256>>>(a0, a1, w0p, md0, relu0);
    cudaStreamWaitEvent(0, ev2a, 0);  // join: w1 pack + bias1 ready
    // L1 main: exactly 5 tiles per CTA-slot (304*5 = 1520), zero tail
    k_mmap<16, false><<<304, 256, SM16>>>(a1, HP1, a2, nullptr,
        128, 128, HP2, 192, w1p, 1, md1, relu1, nullptr, 1520, 0, 1);
    // L1 tail: TC16 idx 1520..1535 == TC8 idx 3040..3071 (verified decode)
    k_mmap<8, false><<<32, 256, SM8>>>(a1, HP1, a2, nullptr,
        128, 128, HP2, 192, w1p, 1, md1, relu1, nullptr, 3072, 3040, 5);
    cudaStreamWaitEvent(0, ev2b, 0);  // join: w2/w3 packs + fills + biases ready
    k_mmap<8, false><<<304, 256, SM8>>>(a2, HP2, a3, nullptr,
        64, 64, HP3, 192, w2p, 2, md2, relu2, nullptr, 768, 0, 2);
    k_mmap<8, true><<<304, 256, SM8>>>(a3, HP3, nullptr, (float*)d_out,
        32, 32, 0, 320, w3p, 3, md3, nullptr, ga, 320, 0, 3);
}

// round 16
// speedup vs baseline: 1.0379x; 1.0068x over previous
#include <cuda_runtime.h>
#include <cstdint>

typedef signed char s8;

#define HP0 516
#define HP1 260
#define HP2 132
#define HP3 68

// a0: [n][HP0][HP0][4] (u8-offset s8, pad=-128). a1..a3: chunk-major
// [n][c=IC/32][Hp][Wp][32] so 32B ic-chunks are contiguous across pixels.
__device__ __align__(16) s8 g_a0[4 * HP0 * HP0 * 4];
__device__ __align__(16) s8 g_a1[4 * HP1 * HP1 * 192];
__device__ __align__(16) s8 g_a2[4 * HP2 * HP2 * 192];
__device__ __align__(16) s8 g_a3[4 * HP3 * HP3 * 192];
__device__ __align__(16) s8 g_w0[192 * 25 * 4];
// mma fragment-packed weights: [octile64][chunk32][tap25][tp4][lane32][16B]
__device__ __align__(16) s8 g_w1[192 * 25 * 192];
__device__ __align__(16) s8 g_w2[192 * 25 * 192];
__device__ __align__(16) s8 g_w3[320 * 25 * 192];
__device__ int g_beff[4][320];
__device__ int g_muli[4][320];
__device__ int g_ctr[8];  // work-stealing counters, zeroed in k_prep1

__device__ __forceinline__ int ld_scalar(const int* p) {
    int v = *p;
    if ((unsigned)v >= 0x3f000000u) v = (int)rintf(__int_as_float(v));
    return v;
}

#define CP_ASYNC16(dst, src) \
    asm volatile("cp.async.cg.shared.global [%0], [%1], 16;" :: "r"(dst), "l"(src))
#define CP_ASYNC8(dst, src) \
    asm volatile("cp.async.ca.shared.global [%0], [%1], 8;" :: "r"(dst), "l"(src))
#define CP_COMMIT() asm volatile("cp.async.commit_group;" ::: "memory")
#define CP_WAIT1() asm volatile("cp.async.wait_group 1;" ::: "memory")

// ---------------- prep device helpers ----------------

__device__ __forceinline__ void d_quant(const float* __restrict__ x, int idx) {
    if (idx >= 4 * HP0 * HP0) return;
    int xp = idx % HP0;
    int t = idx / HP0;
    int yp = t % HP0;
    int n = t / HP0;
    unsigned v = 0x80808080u;
    if (yp >= 2 && yp < 514 && xp >= 2 && xp < 514) {
        int y = yp - 2, xx = xp - 2;
        unsigned b[3];
#pragma unroll
        for (int c = 0; c < 3; c++) {
            float f = x[((n * 3 + c) * 512 + y) * 512 + xx];
            float r = fminf(fmaxf(rintf(f * 256.f), 0.f), 255.f);
            b[c] = (unsigned)(((int)r - 128) & 0xff);
        }
        v = b[0] | (b[1] << 8) | (b[2] << 16) | 0x80000000u;
    }
    ((unsigned*)g_a0)[idx] = v;
}

// Fill only the 2-pixel pad border of a chunk-major buffer.
__device__ __forceinline__ void d_fillb(s8* buf, int Hp, int idx) {
    const int bw = Hp * Hp - (Hp - 4) * (Hp - 4);
    if (idx >= 24 * bw) return;
    int plane = idx / bw;
    int o = idx - plane * bw;
    const int top = 2 * Hp;
    int y, x;
    if (o < top) { y = o / Hp; x = o - (o / Hp) * Hp; }
    else if (o < 2 * top) { int t = o - top; y = Hp - 2 + t / Hp; x = t - (t / Hp) * Hp; }
    else { int t = o - 2 * top; int row = t >> 2; int c = t & 3;
           y = 2 + row; x = (c < 2) ? c : Hp - 4 + c; }
    uint4 v; v.x = v.y = v.z = v.w = 0x80808080u;
    uint4* p = (uint4*)(buf + (((size_t)plane * Hp + y) * Hp + x) * 32);
    p[0] = v; p[1] = v;
}

// paired-t fragment pack: byte idx -> [ot][ch][tap][tp][lane][half][word][j]
__device__ __forceinline__ void d_packb(const float* __restrict__ w,
                                        s8* __restrict__ wp, int idx, int total,
                                        int ICin) {
    if (idx >= total) return;
    int j = idx & 3;
    int word = (idx >> 2) & 1;
    int half = (idx >> 3) & 1;
    int l = (idx >> 4) & 31;
    int tp = (idx >> 9) & 3;
    int rest = idx >> 11;
    int tap = rest % 25; rest /= 25;
    int ch = rest % 6;
    int ot = rest / 6;
    int t = tp * 2 + half;
    int oc = ot * 64 + t * 8 + (l >> 2);
    int ic = ch * 32 + (l & 3) * 4 + word * 16 + j;
    wp[idx] = (s8)(int)rintf(w[(oc * ICin + ic) * 25 + tap]);
}

__device__ __forceinline__ void d_bias(const float* __restrict__ w,
                                       const float* __restrict__ bsrc,
                                       const float* __restrict__ mul, int layer,
                                       int ICin, int* red, int oc, int tid) {
    const float* wr = w + (size_t)oc * ICin * 25;
    int s = 0;
    for (int k = tid; k < ICin * 25; k += 256) s += (int)rintf(wr[k]);
    red[tid] = s;
    __syncthreads();
    for (int st = 128; st > 0; st >>= 1) {
        if (tid < st) red[tid] += red[tid + st];
        __syncthreads();
    }
    if (tid == 0) {
        g_beff[layer][oc] = (int)rintf(bsrc[oc]) + 128 * red[0];
        g_muli[layer][oc] = (int)rintf(mul[oc]);
    }
}

// prep1 (critical path): ctr reset + quant + border-fill a1 + layer0 pack/bias
__global__ void __launch_bounds__(256) k_prep1(
    const float* __restrict__ x, const float* __restrict__ w0,
    const float* __restrict__ b0, const float* __restrict__ mul0) {
    const int tid = threadIdx.x;
    int b = blockIdx.x;
    if (b < 4161) {
        if (b == 0 && tid < 8) g_ctr[tid] = 0;
        d_quant(x, b * 256 + tid);
        return;
    }
    b -= 4161;
    if (b < 194) { d_fillb(g_a1, HP1, b * 256 + tid); return; }
    b -= 194;
    {
        int pidx = b * 256 + tid;
        if (pidx < 192 * 25 * 4) {
            int byte = pidx & 3;
            int t = pidx >> 2;
            int oc_l = t & 63; t >>= 6;
            int tap = t % 25; t /= 25;
            int oc = t * 64 + oc_l;
            s8 val = 0;
            if (byte < 3) val = (s8)(int)rintf(w0[(oc * 3 + byte) * 25 + tap]);
            g_w0[pidx] = val;
        }
        if (pidx < 192) {
            const float* wr = w0 + (size_t)pidx * 75;
            int s = 0;
            for (int k = 0; k < 75; k++) s += (int)rintf(wr[k]);
            g_beff[0][pidx] = (int)rintf(b0[pidx] * 256.f) + 128 * s;
            g_muli[0][pidx] = (int)rintf(mul0[pidx]);
        }
    }
}

// prep2a (forked stream, joined before L1): w1 pack + bias1. 3600+192 = 3792 blocks
__global__ void __launch_bounds__(256) k_prep2a(
    const float* __restrict__ w1, const float* __restrict__ b1,
    const float* __restrict__ mul1) {
    const int tid = threadIdx.x;
    int b = blockIdx.x;
    __shared__ int red[256];
    if (b < 3600) { d_packb(w1, g_w1, b * 256 + tid, 921600, 192); return; }
    b -= 3600;
    d_bias(w1, b1, mul1, 1, 192, red, b, tid);
}

// prep2b (forked stream, joined before L2): fills a2/a3 + w2/w3 pack + bias2/3
// 98 + 50 + 3600 + 6000 + 192 + 320 = 10260 blocks
__global__ void __launch_bounds__(256) k_prep2b(
    const float* __restrict__ w2, const float* __restrict__ b2,
    const float* __restrict__ mul2, const float* __restrict__ w3,
    const float* __restrict__ b3, const float* __restrict__ mul3) {
    const int tid = threadIdx.x;
    int b = blockIdx.x;
    __shared__ int red[256];
    if (b < 98) { d_fillb(g_a2, HP2, b * 256 + tid); return; }
    b -= 98;
    if (b < 50) { d_fillb(g_a3, HP3, b * 256 + tid); return; }
    b -= 50;
    if (b < 3600) { d_packb(w2, g_w2, b * 256 + tid, 921600, 192); return; }
    b -= 3600;
    if (b < 6000) { d_packb(w3, g_w3, b * 256 + tid, 1536000, 192); return; }
    b -= 6000;
    if (b < 192) { d_bias(w2, b2, mul2, 2, 192, red, b, tid); return; }
    b -= 192;
    d_bias(w3, b3, mul3, 3, 192, red, b, tid);
}

// ---------------- layer 0: dp4a implicit conv (IC=4), int32 epilogue ------
__global__ void __launch_bounds__(256)
k_conv0(const s8* __restrict__ in, s8* __restrict__ out8,
        const s8* __restrict__ wgt,
        const int* __restrict__ mdp, const int* __restrict__ relup) {
    __shared__ __align__(16) int sW[25 * 64];
    __shared__ int sA[665];

    const int tid = threadIdx.x;
    const int r = tid >> 4;
    const int c = tid & 15;
    const int py = c & 7;
    const int x0 = (c >> 3) << 3;

    const int ocb = blockIdx.x << 6;
    const int by = blockIdx.y >> 4;
    const int bx = blockIdx.y & 15;
    const int oy0 = by << 3;
    const int ox0 = bx << 4;
    const int n = blockIdx.z;

    int acc[4][8];
#pragma unroll
    for (int i = 0; i < 4; i++)
#pragma unroll
        for (int j = 0; j < 8; j++) acc[i][j] = 0;

    const int aBase = (2 * py) * 35 + 2 * x0;
    const int iy0 = 2 * oy0, ix0 = 2 * ox0;

    {
        const int4* wsrc = (const int4*)(wgt + (size_t)blockIdx.x * (25 * 256));
        int4* wdst = (int4*)sW;
        for (int idx = tid; idx < 25 * 16; idx += 256) wdst[idx] = wsrc[idx];
        for (int idx = tid; idx < 665; idx += 256) {
            int iy = idx / 35, ix = idx - iy * 35;
            sA[idx] = *(const int*)(in + ((size_t)(n * HP0 + iy0 + iy) * HP0 + ix0 + ix) * 4);
        }
    }
    __syncthreads();

#pragma unroll
    for (int ky = 0; ky < 5; ky++)
#pragma unroll
        for (int kx = 0; kx < 5; kx++) {
            const int tap = ky * 5 + kx;
            const int4 w = ((const int4*)sW)[tap * 16 + r];
            const int* arow = &sA[ky * 35 + kx + aBase];
#pragma unroll
            for (int j = 0; j < 8; j++) {
                const int a = arow[2 * j];
                acc[0][j] = __dp4a(a, w.x, acc[0][j]);
                acc[1][j] = __dp4a(a, w.y, acc[1][j]);
                acc[2][j] = __dp4a(a, w.z, acc[2][j]);
                acc[3][j] = __dp4a(a, w.w, acc[3][j]);
            }
        }

    const int oy = oy0 + py;
    const int oxb = ox0 + x0;
    const int md = ld_scalar(mdp);
    const int relu = ld_scalar(relup);
    const int clp = (int)rint(255.0 * 16777216.0 / (double)relu);
    const int scl = (relu + 4) >> 3;
    const int sh1 = md;
    const int rnd1 = 1 << (sh1 - 1);

    int b[4], m[4];
#pragma unroll
    for (int i = 0; i < 4; i++) {
        int oc = ocb + r * 4 + i;
        b[i] = g_beff[0][oc];
        m[i] = g_muli[0][oc];
    }
    const int oc0 = ocb + r * 4;
    const int cch = oc0 >> 5;
    s8* obase = out8 + ((size_t)(n * 6 + cch) * HP1 + (oy + 2)) * (HP1 * 32) + (oc0 & 31);
#pragma unroll
    for (int j = 0; j < 8; j++) {
        unsigned pack = 0;
#pragma unroll
        for (int i = 0; i < 4; i++) {
            int v = (acc[i][j] + b[i]) * m[i];
            v = (v + rnd1) >> sh1;
            v = v < 0 ? 0 : (v > clp ? clp : v);
            v = (v * scl + (1 << 20)) >> 21;
            pack |= ((unsigned)((v - 128) & 0xff)) << (8 * i);
        }
        *(unsigned*)(obase + (size_t)(oxb + j + 2) * 32) = pack;
    }
}

// ---------------- layers 1-3: persistent pipelined int8 TC conv ----------
__device__ __forceinline__ void mma16832(int (&d)[4], const unsigned (&a)[4],
                                         unsigned bx, unsigned by) {
    asm volatile(
        "mma.sync.aligned.m16n8k32.row.col.s32.s8.s8.s32 "
        "{%0,%1,%2,%3}, {%4,%5,%6,%7}, {%8,%9}, {%0,%1,%2,%3};"
        : "+r"(d[0]), "+r"(d[1]), "+r"(d[2]), "+r"(d[3])
        : "r"(a[0]), "r"(a[1]), "r"(a[2]), "r"(a[3]), "r"(bx), "r"(by));
}

// TC=16: tile 8x16 px x 64 oc. TC=8: tile 8x8 px x 64 oc, warp pairs.
// Single-barrier 3-deep B ring (5-tap groups), A double-buffered.
// Work stealing: idx = base + atomicAdd(g_ctr[slot]); continue while idx < n_tiles.
#define BGRP 10240

template <int TC, bool FINAL>
__global__ void __launch_bounds__(256, 2)
k_mmap(const s8* __restrict__ in, int Hp,
       s8* __restrict__ out8, float* __restrict__ outf,
       int Hout, int Wout, int Hpo, int OC,
       const s8* __restrict__ wgt, int layer,
       const int* __restrict__ mdp, const int* __restrict__ relup,
       const int* __restrict__ gap, int n_tiles, int base, int slot) {
    constexpr bool PAIR = (TC == 8);
    constexpr int PCOLS = 2 * TC + 3;
    constexpr int NPIX = 19 * PCOLS;
    constexpr int ASZ = (NPIX * 40 + 127) & ~127;
    constexpr int BOFF = 2 * ASZ;
    constexpr int NT = PAIR ? 4 : 8;

    extern __shared__ __align__(16) unsigned char smem[];
    const uint32_t smem_sm = (uint32_t)__cvta_generic_to_shared(smem);
    __shared__ int s_tile;

    const int tid = threadIdx.x;
    const int w = tid >> 5;
    const int lane = tid & 31;
    const int gr = lane >> 2;
    const int qp = lane & 3;
    const int wp = PAIR ? (w & 3) : w;
    const int hi = PAIR ? (w >> 2) : 0;

    const int tiles_x = Wout / TC;
    const int tiles_y = Hout >> 3;
    const int per_oct = tiles_y * tiles_x * 4;

    const int md = ld_scalar(mdp);
    int ga = 0, relu = 0;
    if (FINAL) ga = ld_scalar(gap);
    else relu = ld_scalar(relup);

    const int abase = PAIR ? (((wp * 4) * PCOLS + (gr << 1)) * 10 + qp)
                           : (((w * 2) * PCOLS + (gr << 1)) * 10 + qp);
    constexpr int A1OFF = PAIR ? (2 * PCOLS * 10) : 160;
    int* ctr = &g_ctr[slot];

    while (true) {
        if (tid == 0) s_tile = base + atomicAdd(ctr, 1);
        __syncthreads();
        const int idx = s_tile;
        if (idx >= n_tiles) break;

        const int oct = idx / per_oct;
        int r1 = idx - oct * per_oct;
        const int by = r1 / (tiles_x * 4);
        int r2 = r1 - by * (tiles_x * 4);
        const int bx = r2 >> 2;
        const int n = r2 & 3;

        const int ocb = oct << 6;
        const int oy0 = by << 3;
        const int ox0 = bx * TC;
        const int iy0 = oy0 << 1, ix0 = ox0 << 1;

        int acc[NT][4];
#pragma unroll
        for (int t = 0; t < NT; t++)
#pragma unroll
            for (int k = 0; k < 4; k++) acc[t][k] = 0;

        const s8* wbase = wgt + (size_t)oct * 6 * 51200;
        {
            const int4* bs = (const int4*)wbase;
            for (int i = tid; i < 640; i += 256)
                CP_ASYNC16(smem_sm + BOFF + i * 16, bs + i);
            const s8* base_a =
                in + ((size_t)(n * 6 + 0) * Hp + iy0) * (size_t)(Hp * 32) +
                (size_t)ix0 * 32;
            for (int v = tid; v < NPIX * 4; v += 256) {
                int pix = v >> 2, part = v & 3;
                int iy = pix / PCOLS, ix = pix - iy * PCOLS;
                CP_ASYNC8(smem_sm + pix * 40 + part * 8,
                          base_a + ((size_t)iy * Hp + ix) * 32 + part * 8);
            }
            CP_COMMIT();
            const int4* bs1 = (const int4*)(wbase + BGRP);
            for (int i = tid; i < 640; i += 256)
                CP_ASYNC16(smem_sm + BOFF + BGRP + i * 16, bs1 + i);
            CP_COMMIT();
        }

        for (int u = 0; u < 30; u++) {
            CP_WAIT1();
            __syncthreads();
            if (u + 2 < 30) {
                const int un = u + 2;
                const int nch = un / 5, ng = un % 5;
                const int4* bs = (const int4*)(wbase + (size_t)nch * 51200 + ng * BGRP);
                const uint32_t bdst = smem_sm + BOFF + (un % 3) * BGRP;
                for (int i = tid; i < 640; i += 256)
                    CP_ASYNC16(bdst + i * 16, bs + i);
                if (ng == 0) {
                    const uint32_t adst = smem_sm + (nch & 1) * ASZ;
                    const s8* base_a =
                        in + ((size_t)(n * 6 + nch) * Hp + iy0) * (size_t)(Hp * 32) +
                        (size_t)ix0 * 32;
                    for (int v = tid; v < NPIX * 4; v += 256) {
                        int pix = v >> 2, part = v & 3;
                        int iy = pix / PCOLS, ix = pix - iy * PCOLS;
                        CP_ASYNC8(adst + pix * 40 + part * 8,
                                  base_a + ((size_t)iy * Hp + ix) * 32 + part * 8);
                    }
                }
            }
            CP_COMMIT();

            const int ch = u / 5, g = u % 5;
            const unsigned* aB = (const unsigned*)(smem + (ch & 1) * ASZ);
            const unsigned char* bB = smem + BOFF + (u % 3) * BGRP;
#pragma unroll
            for (int k = 0; k < 5; k++) {
                const unsigned* ap = aB + abase + (g * PCOLS + k) * 10;
                unsigned a[4];
                a[0] = ap[0];
                a[2] = ap[4];
                a[1] = ap[A1OFF];
                a[3] = ap[A1OFF + 4];
                const uint4* bq = (const uint4*)(bB + k * 2048) + lane;
                if (PAIR) {
#pragma unroll
                    for (int tp2 = 0; tp2 < 2; tp2++) {
                        uint4 bb = bq[(hi * 2 + tp2) * 32];
                        mma16832(acc[2 * tp2], a, bb.x, bb.y);
                        mma16832(acc[2 * tp2 + 1], a, bb.z, bb.w);
                    }
                } else {
#pragma unroll
                    for (int tp = 0; tp < 4; tp++) {
                        uint4 bb = bq[tp * 32];
                        mma16832(acc[2 * tp], a, bb.x, bb.y);
                        mma16832(acc[2 * tp + 1], a, bb.z, bb.w);
                    }
                }
            }
        }

        if (FINAL) {
            const int sh = md - ga;
            const long long rnd = 1LL << (sh - 1);
#pragma unroll
            for (int t = 0; t < NT; t++) {
                int tg = PAIR ? (4 * hi + t) : t;
                int oc = ocb + tg * 8 + 2 * qp;
                int2 bb = *(const int2*)&g_beff[layer][oc];
                int2 mm = *(const int2*)&g_muli[layer][oc];
#pragma unroll
                for (int half = 0; half < 2; half++) {
                    int oy = PAIR ? (oy0 + 2 * wp + half) : (oy0 + w);
                    int ox = PAIR ? (ox0 + gr) : (ox0 + gr + half * 8);
                    long long v0 = ((long long)acc[t][half * 2] + bb.x) * mm.x;
                    long long v1 = ((long long)acc[t][half * 2 + 1] + bb.y) * mm.y;
                    v0 = (v0 + rnd) >> sh;
                    v1 = (v1 + rnd) >> sh;
                    outf[(((size_t)n * OC + oc) * Hout + oy) * Wout + ox] = (float)v0;
                    outf[(((size_t)n * OC + oc + 1) * Hout + oy) * Wout + ox] = (float)v1;
                }
            }
        } else {
            const long long clp = (long long)rint(255.0 * 16777216.0 / (double)relu);
            const long long scl = (long long)((relu + 4) >> 3);
            const int sh1 = md - 8;
            const long long rnd1 = 1LL << (sh1 - 1);
#pragma unroll
            for (int t = 0; t < NT; t++) {
                int tg = PAIR ? (4 * hi + t) : t;
                int oc = ocb + tg * 8 + 2 * qp;
                int2 bb = *(const int2*)&g_beff[layer][oc];
                int2 mm = *(const int2*)&g_muli[layer][oc];
                s8* ob = out8 + ((size_t)(n * 6 + (oc >> 5)) * Hpo) * (size_t)(Hpo * 32) +
                         (oc & 31);
#pragma unroll
                for (int half = 0; half < 2; half++) {
                    int oy = PAIR ? (oy0 + 2 * wp + half) : (oy0 + w);
                    int ox = PAIR ? (ox0 + gr) : (ox0 + gr + half * 8);
                    long long v0 = ((long long)acc[t][half * 2] + bb.x) * mm.x;
                    long long v1 = ((long long)acc[t][half * 2 + 1] + bb.y) * mm.y;
                    v0 = (v0 + rnd1) >> sh1;
                    v1 = (v1 + rnd1) >> sh1;
                    v0 = v0 < 0 ? 0 : (v0 > clp ? clp : v0);
                    v1 = v1 < 0 ? 0 : (v1 > clp ? clp : v1);
                    v0 = (v0 * scl + (1LL << 20)) >> 21;
                    v1 = (v1 * scl + (1LL << 20)) >> 21;
                    unsigned short pk =
                        (unsigned short)(((unsigned)((v0 - 128) & 0xff)) |
                                         (((unsigned)((v1 - 128) & 0xff)) << 8));
                    *(unsigned short*)(ob + ((size_t)(oy + 2) * Hpo + (ox + 2)) * 32) = pk;
                }
            }
        }
    }
}

extern "C" void kernel_launch(void* const* d_in, const int* in_sizes, int n_in,
                              void* d_out, int out_size) {
    const float* x = (const float*)d_in[0];
    const float* w0 = (const float*)d_in[1];
    const float* b0 = (const float*)d_in[2];
    const float* w1 = (const float*)d_in[3];
    const float* b1 = (const float*)d_in[4];
    const float* w2 = (const float*)d_in[5];
    const float* b2 = (const float*)d_in[6];
    const float* w3 = (const float*)d_in[7];
    const float* b3 = (const float*)d_in[8];
    const float* mul0 = (const float*)d_in[9];
    const float* mul1 = (const float*)d_in[10];
    const float* mul2 = (const float*)d_in[11];
    const float* mul3 = (const float*)d_in[12];
    const int* relu0 = (const int*)d_in[13];
    const int* relu1 = (const int*)d_in[14];
    const int* relu2 = (const int*)d_in[15];
    const int* md0 = (const int*)d_in[16];
    const int* md1 = (const int*)d_in[17];
    const int* md2 = (const int*)d_in[18];
    const int* md3 = (const int*)d_in[19];
    const int* ga = (const int*)d_in[20];
    (void)in_sizes; (void)n_in; (void)out_size;

    static s8 *a0 = nullptr, *a1, *a2, *a3, *w0p, *w1p, *w2p, *w3p;
    static cudaStream_t s2 = nullptr, s3 = nullptr;
    static cudaEvent_t ev0 = nullptr, ev2a = nullptr, ev2b = nullptr,
                       evc0 = nullptr, evtail = nullptr;
    const int SM16 = 2 * 26624 + 3 * BGRP;   // 83968
    const int SM8 = 2 * 14464 + 3 * BGRP;    // 59648
    if (!a0) {
        cudaGetSymbolAddress((void**)&a0, g_a0);
        cudaGetSymbolAddress((void**)&a1, g_a1);
        cudaGetSymbolAddress((void**)&a2, g_a2);
        cudaGetSymbolAddress((void**)&a3, g_a3);
        cudaGetSymbolAddress((void**)&w0p, g_w0);
        cudaGetSymbolAddress((void**)&w1p, g_w1);
        cudaGetSymbolAddress((void**)&w2p, g_w2);
        cudaGetSymbolAddress((void**)&w3p, g_w3);
        cudaStreamCreateWithFlags(&s2, cudaStreamNonBlocking);
        cudaStreamCreateWithFlags(&s3, cudaStreamNonBlocking);
        cudaEventCreateWithFlags(&ev0, cudaEventDisableTiming);
        cudaEventCreateWithFlags(&ev2a, cudaEventDisableTiming);
        cudaEventCreateWithFlags(&ev2b, cudaEventDisableTiming);
        cudaEventCreateWithFlags(&evc0, cudaEventDisableTiming);
        cudaEventCreateWithFlags(&evtail, cudaEventDisableTiming);
        cudaFuncSetAttribute(k_mmap<16, false>,
                             cudaFuncAttributeMaxDynamicSharedMemorySize, SM16);
        cudaFuncSetAttribute(k_mmap<8, false>,
                             cudaFuncAttributeMaxDynamicSharedMemorySize, SM8);
        cudaFuncSetAttribute(k_mmap<8, true>,
                             cudaFuncAttributeMaxDynamicSharedMemorySize, SM8);
    }

    // fork s2: prep2a (L1 deps) then prep2b (L2/L3 deps)
    cudaEventRecord(ev0, 0);
    cudaStreamWaitEvent(s2, ev0, 0);
    k_prep2a<<<3792, 256, 0, s2>>>(w1, b1, mul1);
    cudaEventRecord(ev2a, s2);
    k_prep2b<<<10260, 256, 0, s2>>>(w2, b2, mul2, w3, b3, mul3);
    cudaEventRecord(ev2b, s2);

    k_prep1<<<4430, 256>>>(x, w0, b0, mul0);
    k_conv0<<<dim3(3, 512, 4), 256>>>(a0, a1, w0p, md0, relu0);
    cudaEventRecord(evc0, 0);

    // L1 tail on s3, CONCURRENT with L1 main (disjoint a2 regions):
    // TC16 idx 1520..1535 == TC8 idx 3040..3071 (verified decode)
    cudaStreamWaitEvent(s3, evc0, 0);
    cudaStreamWaitEvent(s3, ev2a, 0);
    k_mmap<8, false><<<32, 256, SM8, s3>>>(a1, HP1, a2, nullptr,
        128, 128, HP2, 192, w1p, 1, md1, relu1, nullptr, 3072, 3040, 5);
    cudaEventRecord(evtail, s3);

    // L1 main: exactly 5 tiles per CTA-slot (304*5 = 1520), zero tail
    cudaStreamWaitEvent(0, ev2a, 0);
    k_mmap<16, false><<<304, 256, SM16>>>(a1, HP1, a2, nullptr,
        128, 128, HP2, 192, w1p, 1, md1, relu1, nullptr, 1520, 0, 1);

    cudaStreamWaitEvent(0, evtail, 0);  // a2 fully written
    cudaStreamWaitEvent(0, ev2b, 0);    // w2/w3 packs + fills + biases ready
    k_mmap<8, false><<<304, 256, SM8>>>(a2, HP2, a3, nullptr,
        64, 64, HP3, 192, w2p, 2, md2, relu2, nullptr, 768, 0, 2);
    k_mmap<8, true><<<304, 256, SM8>>>(a3, HP3, nullptr, (float*)d_out,
        32, 32, 0, 320, w3p, 3, md3, nullptr, ga, 320, 0, 3);
}

// round 17
// speedup vs baseline: 1.0542x; 1.0156x over previous
#include <cuda_runtime.h>
#include <cstdint>

typedef signed char s8;

#define HP0 516
#define HP1 260
#define HP2 132
#define HP3 68

// a0: [n][HP0][HP0][4] (u8-offset s8, pad=-128). a1..a3: chunk-major
// [n][c=IC/32][Hp][Wp][32] so 32B ic-chunks are contiguous across pixels.
__device__ __align__(16) s8 g_a0[4 * HP0 * HP0 * 4];
__device__ __align__(16) s8 g_a1[4 * HP1 * HP1 * 192];
__device__ __align__(16) s8 g_a2[4 * HP2 * HP2 * 192];
__device__ __align__(16) s8 g_a3[4 * HP3 * HP3 * 192];
__device__ __align__(16) s8 g_w0[192 * 25 * 4];
// mma fragment-packed weights: [octile64][chunk32][tap25][tp4][lane32][16B]
__device__ __align__(16) s8 g_w1[192 * 25 * 192];
__device__ __align__(16) s8 g_w2[192 * 25 * 192];
__device__ __align__(16) s8 g_w3[320 * 25 * 192];
__device__ int g_beff[4][320];
__device__ int g_muli[4][320];
__device__ int g_ctr[8];  // work-stealing counters, zeroed in k_prep1

__device__ __forceinline__ int ld_scalar(const int* p) {
    int v = *p;
    if ((unsigned)v >= 0x3f000000u) v = (int)rintf(__int_as_float(v));
    return v;
}

#define CP_ASYNC16(dst, src) \
    asm volatile("cp.async.cg.shared.global [%0], [%1], 16;" :: "r"(dst), "l"(src))
#define CP_ASYNC8(dst, src) \
    asm volatile("cp.async.ca.shared.global [%0], [%1], 8;" :: "r"(dst), "l"(src))
#define CP_COMMIT() asm volatile("cp.async.commit_group;" ::: "memory")
#define CP_WAIT1() asm volatile("cp.async.wait_group 1;" ::: "memory")

// ---------------- prep device helpers ----------------

__device__ __forceinline__ void d_quant(const float* __restrict__ x, int idx) {
    if (idx >= 4 * HP0 * HP0) return;
    int xp = idx % HP0;
    int t = idx / HP0;
    int yp = t % HP0;
    int n = t / HP0;
    unsigned v = 0x80808080u;
    if (yp >= 2 && yp < 514 && xp >= 2 && xp < 514) {
        int y = yp - 2, xx = xp - 2;
        unsigned b[3];
#pragma unroll
        for (int c = 0; c < 3; c++) {
            float f = x[((n * 3 + c) * 512 + y) * 512 + xx];
            float r = fminf(fmaxf(rintf(f * 256.f), 0.f), 255.f);
            b[c] = (unsigned)(((int)r - 128) & 0xff);
        }
        v = b[0] | (b[1] << 8) | (b[2] << 16) | 0x80000000u;
    }
    ((unsigned*)g_a0)[idx] = v;
}

// Fill only the 2-pixel pad border of a chunk-major buffer.
__device__ __forceinline__ void d_fillb(s8* buf, int Hp, int idx) {
    const int bw = Hp * Hp - (Hp - 4) * (Hp - 4);
    if (idx >= 24 * bw) return;
    int plane = idx / bw;
    int o = idx - plane * bw;
    const int top = 2 * Hp;
    int y, x;
    if (o < top) { y = o / Hp; x = o - (o / Hp) * Hp; }
    else if (o < 2 * top) { int t = o - top; y = Hp - 2 + t / Hp; x = t - (t / Hp) * Hp; }
    else { int t = o - 2 * top; int row = t >> 2; int c = t & 3;
           y = 2 + row; x = (c < 2) ? c : Hp - 4 + c; }
    uint4 v; v.x = v.y = v.z = v.w = 0x80808080u;
    uint4* p = (uint4*)(buf + (((size_t)plane * Hp + y) * Hp + x) * 32);
    p[0] = v; p[1] = v;
}

// paired-t fragment pack: byte idx -> [ot][ch][tap][tp][lane][half][word][j]
__device__ __forceinline__ void d_packb(const float* __restrict__ w,
                                        s8* __restrict__ wp, int idx, int total,
                                        int ICin) {
    if (idx >= total) return;
    int j = idx & 3;
    int word = (idx >> 2) & 1;
    int half = (idx >> 3) & 1;
    int l = (idx >> 4) & 31;
    int tp = (idx >> 9) & 3;
    int rest = idx >> 11;
    int tap = rest % 25; rest /= 25;
    int ch = rest % 6;
    int ot = rest / 6;
    int t = tp * 2 + half;
    int oc = ot * 64 + t * 8 + (l >> 2);
    int ic = ch * 32 + (l & 3) * 4 + word * 16 + j;
    wp[idx] = (s8)(int)rintf(w[(oc * ICin + ic) * 25 + tap]);
}

__device__ __forceinline__ void d_bias(const float* __restrict__ w,
                                       const float* __restrict__ bsrc,
                                       const float* __restrict__ mul, int layer,
                                       int ICin, int* red, int oc, int tid) {
    const float* wr = w + (size_t)oc * ICin * 25;
    int s = 0;
    for (int k = tid; k < ICin * 25; k += 256) s += (int)rintf(wr[k]);
    red[tid] = s;
    __syncthreads();
    for (int st = 128; st > 0; st >>= 1) {
        if (tid < st) red[tid] += red[tid + st];
        __syncthreads();
    }
    if (tid == 0) {
        g_beff[layer][oc] = (int)rintf(bsrc[oc]) + 128 * red[0];
        g_muli[layer][oc] = (int)rintf(mul[oc]);
    }
}

// prep1 (critical path): ctr reset + quant + border-fill a1 + layer0 pack/bias
__global__ void __launch_bounds__(256) k_prep1(
    const float* __restrict__ x, const float* __restrict__ w0,
    const float* __restrict__ b0, const float* __restrict__ mul0) {
    const int tid = threadIdx.x;
    int b = blockIdx.x;
    if (b < 4161) {
        if (b == 0 && tid < 8) g_ctr[tid] = 0;
        d_quant(x, b * 256 + tid);
        return;
    }
    b -= 4161;
    if (b < 194) { d_fillb(g_a1, HP1, b * 256 + tid); return; }
    b -= 194;
    {
        int pidx = b * 256 + tid;
        if (pidx < 192 * 25 * 4) {
            int byte = pidx & 3;
            int t = pidx >> 2;
            int oc_l = t & 63; t >>= 6;
            int tap = t % 25; t /= 25;
            int oc = t * 64 + oc_l;
            s8 val = 0;
            if (byte < 3) val = (s8)(int)rintf(w0[(oc * 3 + byte) * 25 + tap]);
            g_w0[pidx] = val;
        }
        if (pidx < 192) {
            const float* wr = w0 + (size_t)pidx * 75;
            int s = 0;
            for (int k = 0; k < 75; k++) s += (int)rintf(wr[k]);
            g_beff[0][pidx] = (int)rintf(b0[pidx] * 256.f) + 128 * s;
            g_muli[0][pidx] = (int)rintf(mul0[pidx]);
        }
    }
}

// prep2a (forked stream, joined before L1): w1 pack + bias1. 3600+192 = 3792 blocks
__global__ void __launch_bounds__(256) k_prep2a(
    const float* __restrict__ w1, const float* __restrict__ b1,
    const float* __restrict__ mul1) {
    const int tid = threadIdx.x;
    int b = blockIdx.x;
    __shared__ int red[256];
    if (b < 3600) { d_packb(w1, g_w1, b * 256 + tid, 921600, 192); return; }
    b -= 3600;
    d_bias(w1, b1, mul1, 1, 192, red, b, tid);
}

// prep2b (forked stream, joined before L2): fills a2/a3 + w2/w3 pack + bias2/3
// 98 + 50 + 3600 + 6000 + 192 + 320 = 10260 blocks
__global__ void __launch_bounds__(256) k_prep2b(
    const float* __restrict__ w2, const float* __restrict__ b2,
    const float* __restrict__ mul2, const float* __restrict__ w3,
    const float* __restrict__ b3, const float* __restrict__ mul3) {
    const int tid = threadIdx.x;
    int b = blockIdx.x;
    __shared__ int red[256];
    if (b < 98) { d_fillb(g_a2, HP2, b * 256 + tid); return; }
    b -= 98;
    if (b < 50) { d_fillb(g_a3, HP3, b * 256 + tid); return; }
    b -= 50;
    if (b < 3600) { d_packb(w2, g_w2, b * 256 + tid, 921600, 192); return; }
    b -= 3600;
    if (b < 6000) { d_packb(w3, g_w3, b * 256 + tid, 1536000, 192); return; }
    b -= 6000;
    if (b < 192) { d_bias(w2, b2, mul2, 2, 192, red, b, tid); return; }
    b -= 192;
    d_bias(w3, b3, mul3, 3, 192, red, b, tid);
}

// ---------------- layer 0: dp4a implicit conv (IC=4), int32 epilogue ------
// __launch_bounds__(256,4): force <=64 regs -> 4 CTAs/SM (occ 50% vs 37.5%)
__global__ void __launch_bounds__(256, 4)
k_conv0(const s8* __restrict__ in, s8* __restrict__ out8,
        const s8* __restrict__ wgt,
        const int* __restrict__ mdp, const int* __restrict__ relup) {
    __shared__ __align__(16) int sW[25 * 64];
    __shared__ int sA[665];

    const int tid = threadIdx.x;
    const int r = tid >> 4;
    const int c = tid & 15;
    const int py = c & 7;
    const int x0 = (c >> 3) << 3;

    const int ocb = blockIdx.x << 6;
    const int by = blockIdx.y >> 4;
    const int bx = blockIdx.y & 15;
    const int oy0 = by << 3;
    const int ox0 = bx << 4;
    const int n = blockIdx.z;

    int acc[4][8];
#pragma unroll
    for (int i = 0; i < 4; i++)
#pragma unroll
        for (int j = 0; j < 8; j++) acc[i][j] = 0;

    const int aBase = (2 * py) * 35 + 2 * x0;
    const int iy0 = 2 * oy0, ix0 = 2 * ox0;

    {
        const int4* wsrc = (const int4*)(wgt + (size_t)blockIdx.x * (25 * 256));
        int4* wdst = (int4*)sW;
        for (int idx = tid; idx < 25 * 16; idx += 256) wdst[idx] = wsrc[idx];
        for (int idx = tid; idx < 665; idx += 256) {
            int iy = idx / 35, ix = idx - iy * 35;
            sA[idx] = *(const int*)(in + ((size_t)(n * HP0 + iy0 + iy) * HP0 + ix0 + ix) * 4);
        }
    }
    __syncthreads();

#pragma unroll
    for (int ky = 0; ky < 5; ky++)
#pragma unroll
        for (int kx = 0; kx < 5; kx++) {
            const int tap = ky * 5 + kx;
            const int4 w = ((const int4*)sW)[tap * 16 + r];
            const int* arow = &sA[ky * 35 + kx + aBase];
#pragma unroll
            for (int j = 0; j < 8; j++) {
                const int a = arow[2 * j];
                acc[0][j] = __dp4a(a, w.x, acc[0][j]);
                acc[1][j] = __dp4a(a, w.y, acc[1][j]);
                acc[2][j] = __dp4a(a, w.z, acc[2][j]);
                acc[3][j] = __dp4a(a, w.w, acc[3][j]);
            }
        }

    const int oy = oy0 + py;
    const int oxb = ox0 + x0;
    const int md = ld_scalar(mdp);
    const int relu = ld_scalar(relup);
    const int clp = (int)rint(255.0 * 16777216.0 / (double)relu);
    const int scl = (relu + 4) >> 3;
    const int sh1 = md;
    const int rnd1 = 1 << (sh1 - 1);

    int b[4], m[4];
#pragma unroll
    for (int i = 0; i < 4; i++) {
        int oc = ocb + r * 4 + i;
        b[i] = g_beff[0][oc];
        m[i] = g_muli[0][oc];
    }
    const int oc0 = ocb + r * 4;
    const int cch = oc0 >> 5;
    s8* obase = out8 + ((size_t)(n * 6 + cch) * HP1 + (oy + 2)) * (HP1 * 32) + (oc0 & 31);
#pragma unroll
    for (int j = 0; j < 8; j++) {
        unsigned pack = 0;
#pragma unroll
        for (int i = 0; i < 4; i++) {
            int v = (acc[i][j] + b[i]) * m[i];
            v = (v + rnd1) >> sh1;
            v = v < 0 ? 0 : (v > clp ? clp : v);
            v = (v * scl + (1 << 20)) >> 21;
            pack |= ((unsigned)((v - 128) & 0xff)) << (8 * i);
        }
        *(unsigned*)(obase + (size_t)(oxb + j + 2) * 32) = pack;
    }
}

// ---------------- layers 1-3: persistent pipelined int8 TC conv ----------
__device__ __forceinline__ void mma16832(int (&d)[4], const unsigned (&a)[4],
                                         unsigned bx, unsigned by) {
    asm volatile(
        "mma.sync.aligned.m16n8k32.row.col.s32.s8.s8.s32 "
        "{%0,%1,%2,%3}, {%4,%5,%6,%7}, {%8,%9}, {%0,%1,%2,%3};"
        : "+r"(d[0]), "+r"(d[1]), "+r"(d[2]), "+r"(d[3])
        : "r"(a[0]), "r"(a[1]), "r"(a[2]), "r"(a[3]), "r"(bx), "r"(by));
}

// TC=16: tile 8x16 px x 64 oc. TC=8: tile 8x8 px x 64 oc, warp pairs.
// OCS (TC=8 only): tile 8x8 px x 32 oc (oc-half split, warp-half = 1 tp group).
// Single-barrier 3-deep B ring (5-tap groups), A double-buffered.
#define BGRP 10240

template <int TC, bool FINAL, bool OCS>
__global__ void __launch_bounds__(256, 2)
k_mmap(const s8* __restrict__ in, int Hp,
       s8* __restrict__ out8, float* __restrict__ outf,
       int Hout, int Wout, int Hpo, int OC,
       const s8* __restrict__ wgt, int layer,
       const int* __restrict__ mdp, const int* __restrict__ relup,
       const int* __restrict__ gap, int n_tiles, int base, int slot) {
    constexpr bool PAIR = (TC == 8);
    constexpr int PCOLS = 2 * TC + 3;
    constexpr int NPIX = 19 * PCOLS;
    constexpr int ASZ = (NPIX * 40 + 127) & ~127;
    constexpr int BOFF = 2 * ASZ;
    constexpr int NT = OCS ? 2 : (PAIR ? 4 : 8);
    constexpr int BG = OCS ? 5120 : BGRP;   // bytes per 5-tap group buffer
    constexpr int BTAP = OCS ? 1024 : 2048; // bytes per tap in smem

    extern __shared__ __align__(16) unsigned char smem[];
    const uint32_t smem_sm = (uint32_t)__cvta_generic_to_shared(smem);
    __shared__ int s_tile;

    const int tid = threadIdx.x;
    const int w = tid >> 5;
    const int lane = tid & 31;
    const int gr = lane >> 2;
    const int qp = lane & 3;
    const int wp = PAIR ? (w & 3) : w;
    const int hi = PAIR ? (w >> 2) : 0;

    const int tiles_x = Wout / TC;
    const int tiles_y = Hout >> 3;
    const int per_oct = tiles_y * tiles_x * 4;

    const int md = ld_scalar(mdp);
    int ga = 0, relu = 0;
    if (FINAL) ga = ld_scalar(gap);
    else relu = ld_scalar(relup);

    const int abase = PAIR ? (((wp * 4) * PCOLS + (gr << 1)) * 10 + qp)
                           : (((w * 2) * PCOLS + (gr << 1)) * 10 + qp);
    constexpr int A1OFF = PAIR ? (2 * PCOLS * 10) : 160;
    int* ctr = &g_ctr[slot];

    while (true) {
        if (tid == 0) s_tile = base + atomicAdd(ctr, 1);
        __syncthreads();
        const int idx = s_tile;
        if (idx >= n_tiles) break;

        const int oct = idx / per_oct;   // OCS: oc-half index (2 per 64-oc tile)
        int r1 = idx - oct * per_oct;
        const int by = r1 / (tiles_x * 4);
        int r2 = r1 - by * (tiles_x * 4);
        const int bx = r2 >> 2;
        const int n = r2 & 3;

        const int ocb = OCS ? (((oct >> 1) << 6) + ((oct & 1) << 5)) : (oct << 6);
        const int och = OCS ? (oct & 1) : 0;
        const int oy0 = by << 3;
        const int ox0 = bx * TC;
        const int iy0 = oy0 << 1, ix0 = ox0 << 1;

        int acc[NT][4];
#pragma unroll
        for (int t = 0; t < NT; t++)
#pragma unroll
            for (int k = 0; k < 4; k++) acc[t][k] = 0;

        const s8* wbase = wgt + (size_t)(OCS ? (oct >> 1) : oct) * 6 * 51200;

        // B-group stage for unit un into buffer bdst
        auto stageB = [&](int un, uint32_t bdst) {
            const int nch = un / 5, ng = un % 5;
            if (OCS) {
                for (int i = tid; i < 320; i += 256) {
                    int tap = i >> 6, off = i & 63;
                    const s8* src = wbase + (size_t)nch * 51200 +
                                    (ng * 5 + tap) * 2048 + och * 1024 + off * 16;
                    CP_ASYNC16(bdst + i * 16, src);
                }
            } else {
                const int4* bs = (const int4*)(wbase + (size_t)nch * 51200 + ng * BGRP);
                for (int i = tid; i < 640; i += 256)
                    CP_ASYNC16(bdst + i * 16, bs + i);
            }
        };
        auto stageA = [&](int nch, uint32_t adst) {
            const s8* base_a =
                in + ((size_t)(n * 6 + nch) * Hp + iy0) * (size_t)(Hp * 32) +
                (size_t)ix0 * 32;
            for (int v = tid; v < NPIX * 4; v += 256) {
                int pix = v >> 2, part = v & 3;
                int iy = pix / PCOLS, ix = pix - iy * PCOLS;
                CP_ASYNC8(adst + pix * 40 + part * 8,
                          base_a + ((size_t)iy * Hp + ix) * 32 + part * 8);
            }
        };

        // prologue: unit0 (B + A ch0) then unit1 (B)
        stageB(0, smem_sm + BOFF);
        stageA(0, smem_sm);
        CP_COMMIT();
        stageB(1, smem_sm + BOFF + BG);
        CP_COMMIT();

        for (int u = 0; u < 30; u++) {
            CP_WAIT1();
            __syncthreads();
            if (u + 2 < 30) {
                const int un = u + 2;
                stageB(un, smem_sm + BOFF + (un % 3) * BG);
                if (un % 5 == 0) stageA(un / 5, smem_sm + ((un / 5) & 1) * ASZ);
            }
            CP_COMMIT();

            const int ch = u / 5, g = u % 5;
            const unsigned* aB = (const unsigned*)(smem + (ch & 1) * ASZ);
            const unsigned char* bB = smem + BOFF + (u % 3) * BG;
#pragma unroll
            for (int k = 0; k < 5; k++) {
                const unsigned* ap = aB + abase + (g * PCOLS + k) * 10;
                unsigned a[4];
                a[0] = ap[0];
                a[2] = ap[4];
                a[1] = ap[A1OFF];
                a[3] = ap[A1OFF + 4];
                const uint4* bq = (const uint4*)(bB + k * BTAP) + lane;
                if (OCS) {
                    uint4 bb = bq[hi * 32];
                    mma16832(acc[0], a, bb.x, bb.y);
                    mma16832(acc[1], a, bb.z, bb.w);
                } else if (PAIR) {
#pragma unroll
                    for (int tp2 = 0; tp2 < 2; tp2++) {
                        uint4 bb = bq[(hi * 2 + tp2) * 32];
                        mma16832(acc[2 * tp2], a, bb.x, bb.y);
                        mma16832(acc[2 * tp2 + 1], a, bb.z, bb.w);
                    }
                } else {
#pragma unroll
                    for (int tp = 0; tp < 4; tp++) {
                        uint4 bb = bq[tp * 32];
                        mma16832(acc[2 * tp], a, bb.x, bb.y);
                        mma16832(acc[2 * tp + 1], a, bb.z, bb.w);
                    }
                }
            }
        }

        if (FINAL) {
            const int sh = md - ga;
            const long long rnd = 1LL << (sh - 1);
#pragma unroll
            for (int t = 0; t < NT; t++) {
                int tg = OCS ? (2 * hi + t) : (PAIR ? (4 * hi + t) : t);
                int oc = ocb + tg * 8 + 2 * qp;
                int2 bb = *(const int2*)&g_beff[layer][oc];
                int2 mm = *(const int2*)&g_muli[layer][oc];
#pragma unroll
                for (int half = 0; half < 2; half++) {
                    int oy = PAIR ? (oy0 + 2 * wp + half) : (oy0 + w);
                    int ox = PAIR ? (ox0 + gr) : (ox0 + gr + half * 8);
                    long long v0 = ((long long)acc[t][half * 2] + bb.x) * mm.x;
                    long long v1 = ((long long)acc[t][half * 2 + 1] + bb.y) * mm.y;
                    v0 = (v0 + rnd) >> sh;
                    v1 = (v1 + rnd) >> sh;
                    outf[(((size_t)n * OC + oc) * Hout + oy) * Wout + ox] = (float)v0;
                    outf[(((size_t)n * OC + oc + 1) * Hout + oy) * Wout + ox] = (float)v1;
                }
            }
        } else {
            const long long clp = (long long)rint(255.0 * 16777216.0 / (double)relu);
            const long long scl = (long long)((relu + 4) >> 3);
            const int sh1 = md - 8;
            const long long rnd1 = 1LL << (sh1 - 1);
#pragma unroll
            for (int t = 0; t < NT; t++) {
                int tg = OCS ? (2 * hi + t) : (PAIR ? (4 * hi + t) : t);
                int oc = ocb + tg * 8 + 2 * qp;
                int2 bb = *(const int2*)&g_beff[layer][oc];
                int2 mm = *(const int2*)&g_muli[layer][oc];
                s8* ob = out8 + ((size_t)(n * 6 + (oc >> 5)) * Hpo) * (size_t)(Hpo * 32) +
                         (oc & 31);
#pragma unroll
                for (int half = 0; half < 2; half++) {
                    int oy = PAIR ? (oy0 + 2 * wp + half) : (oy0 + w);
                    int ox = PAIR ? (ox0 + gr) : (ox0 + gr + half * 8);
                    long long v0 = ((long long)acc[t][half * 2] + bb.x) * mm.x;
                    long long v1 = ((long long)acc[t][half * 2 + 1] + bb.y) * mm.y;
                    v0 = (v0 + rnd1) >> sh1;
                    v1 = (v1 + rnd1) >> sh1;
                    v0 = v0 < 0 ? 0 : (v0 > clp ? clp : v0);
                    v1 = v1 < 0 ? 0 : (v1 > clp ? clp : v1);
                    v0 = (v0 * scl + (1LL << 20)) >> 21;
                    v1 = (v1 * scl + (1LL << 20)) >> 21;
                    unsigned short pk =
                        (unsigned short)(((unsigned)((v0 - 128) & 0xff)) |
                                         (((unsigned)((v1 - 128) & 0xff)) << 8));
                    *(unsigned short*)(ob + ((size_t)(oy + 2) * Hpo + (ox + 2)) * 32) = pk;
                }
            }
        }
    }
}

extern "C" void kernel_launch(void* const* d_in, const int* in_sizes, int n_in,
                              void* d_out, int out_size) {
    const float* x = (const float*)d_in[0];
    const float* w0 = (const float*)d_in[1];
    const float* b0 = (const float*)d_in[2];
    const float* w1 = (const float*)d_in[3];
    const float* b1 = (const float*)d_in[4];
    const float* w2 = (const float*)d_in[5];
    const float* b2 = (const float*)d_in[6];
    const float* w3 = (const float*)d_in[7];
    const float* b3 = (const float*)d_in[8];
    const float* mul0 = (const float*)d_in[9];
    const float* mul1 = (const float*)d_in[10];
    const float* mul2 = (const float*)d_in[11];
    const float* mul3 = (const float*)d_in[12];
    const int* relu0 = (const int*)d_in[13];
    const int* relu1 = (const int*)d_in[14];
    const int* relu2 = (const int*)d_in[15];
    const int* md0 = (const int*)d_in[16];
    const int* md1 = (const int*)d_in[17];
    const int* md2 = (const int*)d_in[18];
    const int* md3 = (const int*)d_in[19];
    const int* ga = (const int*)d_in[20];
    (void)in_sizes; (void)n_in; (void)out_size;

    static s8 *a0 = nullptr, *a1, *a2, *a3, *w0p, *w1p, *w2p, *w3p;
    static cudaStream_t s2 = nullptr, s3 = nullptr;
    static cudaEvent_t ev0 = nullptr, ev2a = nullptr, ev2b = nullptr,
                       evc0 = nullptr, evtail = nullptr;
    const int SM16 = 2 * 26624 + 3 * BGRP;   // 83968
    const int SM8 = 2 * 14464 + 3 * BGRP;    // 59648
    const int SM8O = 2 * 14464 + 3 * 5120;   // 44288
    if (!a0) {
        cudaGetSymbolAddress((void**)&a0, g_a0);
        cudaGetSymbolAddress((void**)&a1, g_a1);
        cudaGetSymbolAddress((void**)&a2, g_a2);
        cudaGetSymbolAddress((void**)&a3, g_a3);
        cudaGetSymbolAddress((void**)&w0p, g_w0);
        cudaGetSymbolAddress((void**)&w1p, g_w1);
        cudaGetSymbolAddress((void**)&w2p, g_w2);
        cudaGetSymbolAddress((void**)&w3p, g_w3);
        cudaStreamCreateWithFlags(&s2, cudaStreamNonBlocking);
        cudaStreamCreateWithFlags(&s3, cudaStreamNonBlocking);
        cudaEventCreateWithFlags(&ev0, cudaEventDisableTiming);
        cudaEventCreateWithFlags(&ev2a, cudaEventDisableTiming);
        cudaEventCreateWithFlags(&ev2b, cudaEventDisableTiming);
        cudaEventCreateWithFlags(&evc0, cudaEventDisableTiming);
        cudaEventCreateWithFlags(&evtail, cudaEventDisableTiming);
        cudaFuncSetAttribute(k_mmap<16, false, false>,
                             cudaFuncAttributeMaxDynamicSharedMemorySize, SM16);
        cudaFuncSetAttribute(k_mmap<8, false, false>,
                             cudaFuncAttributeMaxDynamicSharedMemorySize, SM8);
        cudaFuncSetAttribute(k_mmap<8, true, true>,
                             cudaFuncAttributeMaxDynamicSharedMemorySize, SM8O);
    }

    // fork s2: prep2a (L1 deps) then prep2b (L2/L3 deps)
    cudaEventRecord(ev0, 0);
    cudaStreamWaitEvent(s2, ev0, 0);
    k_prep2a<<<3792, 256, 0, s2>>>(w1, b1, mul1);
    cudaEventRecord(ev2a, s2);
    k_prep2b<<<10260, 256, 0, s2>>>(w2, b2, mul2, w3, b3, mul3);
    cudaEventRecord(ev2b, s2);

    k_prep1<<<4430, 256>>>(x, w0, b0, mul0);
    k_conv0<<<dim3(3, 512, 4), 256>>>(a0, a1, w0p, md0, relu0);
    cudaEventRecord(evc0, 0);

    // L1 tail on s3, CONCURRENT with L1 main (disjoint a2 regions)
    cudaStreamWaitEvent(s3, evc0, 0);
    cudaStreamWaitEvent(s3, ev2a, 0);
    k_mmap<8, false, false><<<32, 256, SM8, s3>>>(a1, HP1, a2, nullptr,
        128, 128, HP2, 192, w1p, 1, md1, relu1, nullptr, 3072, 3040, 5);
    cudaEventRecord(evtail, s3);

    // L1 main: exactly 5 tiles per CTA-slot (304*5 = 1520), zero tail
    cudaStreamWaitEvent(0, ev2a, 0);
    k_mmap<16, false, false><<<304, 256, SM16>>>(a1, HP1, a2, nullptr,
        128, 128, HP2, 192, w1p, 1, md1, relu1, nullptr, 1520, 0, 1);

    cudaStreamWaitEvent(0, evtail, 0);  // a2 fully written
    cudaStreamWaitEvent(0, ev2b, 0);    // w2/w3 packs + fills + biases ready
    k_mmap<8, false, false><<<304, 256, SM8>>>(a2, HP2, a3, nullptr,
        64, 64, HP3, 192, w2p, 2, md2, relu2, nullptr, 768, 0, 2);
    // L3: oc-split tiles (8x8 px x 32 oc) -> 640 tiles, finer tail
    k_mmap<8, true, true><<<304, 256, SM8O>>>(a3, HP3, nullptr, (float*)d_out,
        32, 32, 0, 320, w3p, 3, md3, nullptr, ga, 640, 0, 3);
}